// round 11
// baseline (speedup 1.0000x reference)
#include <cuda_runtime.h>
#include <cstdint>

#define BB 256
#define TT 25
#define PRE 2048
#define DD 256
#define K2D 2048
#define NBLK 128
#define STAGES 3

// ---------------- scratch (device globals) ----------------------------------
__device__ float g_x[2][BB * TT * DD];
__device__ float g_h[2][BB * DD];
__device__ float g_c[2][BB * DD];
__device__ float g_att[BB * K2D];
__device__ float g_ad[2][BB * 1024];     // attended att*h (tf32-rounded)
__device__ float g_r[2][BB * DD];        // relu'd reduction output (tf32)
__device__ float g_rp[2][2][BB * DD];    // RED split-K partials [ks][s]
__device__ float g_zzv[2][BB * 1024];    // zz @ V_s, packed-gate layout
__device__ float g_wp[2][512 * 1024];    // permuted [W;U] per stream (tf32)
__device__ float g_wf[2][512 * 1024];    // mab_w @ V_s, packed (tf32)
__device__ float g_bf[2][1024];          // mab_b @ V_s, packed
__device__ float g_attw[512 * K2D];      // att_w (tf32)
__device__ float g_redw[2][1024 * 256];  // red_{v,t}_w (tf32)

__device__ unsigned g_gen_arr[NBLK * 32];   // per-block release lines
__device__ unsigned g_leaf[16 * 32];
__device__ unsigned g_root = 0;

struct RP {
    const float *xv, *xt, *fc0_w, *fc0_b, *fc1_w, *fc1_b;
    const float *lvW, *lvU, *lvV, *lvb, *ltW, *ltU, *ltV, *ltb;
    const float *att_w, *att_b, *red_v_w, *red_v_b, *red_t_w, *red_t_b, *mab_w, *mab_b;
    const float *late0_w, *late0_b, *late1_w, *late1_b;
    float* out;
};

enum { M_FRONT = 0, M_LSTHM, M_ATT, M_RED, M_ZZV, M_PREP };

template <int MODE> __host__ __device__ constexpr int kdim() {
    return MODE == M_FRONT ? 2048 : MODE == M_PREP ? 256 : 512;
}

// ---------------- grid sync (two-level arrive, broadcast release) ------------
__device__ __forceinline__ void gsync() {
    __threadfence();
    __syncthreads();
    if (threadIdx.x == 0) {
        volatile unsigned* mygen = &g_gen_arr[blockIdx.x * 32];
        unsigned gen = *mygen;
        unsigned li = (blockIdx.x & 15) * 32;
        if (atomicAdd(&g_leaf[li], 1u) == 7u) {
            g_leaf[li] = 0;
            __threadfence();
            if (atomicAdd(&g_root, 1u) == 15u) {
                g_root = 0;
                __threadfence();
#pragma unroll 8
                for (int j = 0; j < NBLK; j++)
                    ((volatile unsigned*)g_gen_arr)[j * 32] = gen + 1;
            } else {
                while (*mygen == gen) {}
            }
        } else {
            while (*mygen == gen) {}
        }
    }
    __syncthreads();
}

// ---------------- cp.async / tf32 helpers ------------------------------------
__device__ __forceinline__ void cp16(uint32_t dst, const void* src) {
    asm volatile("cp.async.cg.shared.global [%0], [%1], 16;" :: "r"(dst), "l"(src));
}
__device__ __forceinline__ void cp4(uint32_t dst, const void* src) {
    asm volatile("cp.async.ca.shared.global [%0], [%1], 4;" :: "r"(dst), "l"(src));
}
__device__ __forceinline__ void cpcommit() { asm volatile("cp.async.commit_group;"); }
__device__ __forceinline__ void cpwait1()  { asm volatile("cp.async.wait_group 1;"); }

__device__ __forceinline__ float to_tf32(float x) {
    asm("cvt.rna.tf32.f32 %0, %0;" : "+f"(x));
    return x;
}
__device__ __forceinline__ float sigm(float x) { return 1.0f / (1.0f + expf(-x)); }

__device__ __forceinline__ void mma_tf32(float* acc, const float* a, const float* b) {
    asm volatile(
        "mma.sync.aligned.m16n8k8.row.col.f32.tf32.tf32.f32 "
        "{%0,%1,%2,%3}, {%4,%5,%6,%7}, {%8,%9}, {%0,%1,%2,%3};\n"
        : "+f"(acc[0]), "+f"(acc[1]), "+f"(acc[2]), "+f"(acc[3])
        : "r"(__float_as_uint(a[0])), "r"(__float_as_uint(a[1])),
          "r"(__float_as_uint(a[2])), "r"(__float_as_uint(a[3])),
          "r"(__float_as_uint(b[0])), "r"(__float_as_uint(b[1])));
}

// ---------------- A-row pointer ----------------------------------------------
template <int MODE>
__device__ __forceinline__ const float* rowA(const RP& P, int m, int k, int s, int ks, int t) {
    if constexpr (MODE == M_FRONT)  return (s ? P.xt : P.xv) + (size_t)m * PRE + k;
    else if constexpr (MODE == M_LSTHM)
        return (k < DD) ? g_x[s] + (m * TT + t) * DD + k : g_h[s] + m * DD + (k - DD);
    else if constexpr (MODE == M_ATT)
        return (k < DD) ? g_h[0] + m * DD + k : g_h[1] + m * DD + (k - DD);
    else if constexpr (MODE == M_RED)
        return g_ad[s] + m * 1024 + ks * 512 + k;
    else if constexpr (MODE == M_ZZV)
        return (k < DD) ? g_r[0] + m * DD + k : g_r[1] + m * DD + (k - DD);
    else  // M_PREP: A = mab_w [512 x 256]
        return P.mab_w + (size_t)m * 256 + k;
}

// ---------------- pipelined tf32 MMA GEMM (256 thr, KT=64, 3 stages) ---------
// A stage: BM x 64k, stride 68; B stage: 64k x 64n, stride 72.
template <int MODE, int BM, int BN>
__device__ __forceinline__ void gemm_pipe(const RP& P, int s, int ks, int m0, int n0, int t,
                                          float* smA, float* smB,
                                          uint32_t saA, uint32_t saB) {
    constexpr int KD = kdim<MODE>();
    constexpr int KT = 64;
    constexpr int NITER = KD / KT;
    constexpr int ABUF = BM * 68;
    constexpr int BBUF = KT * 72;
    constexpr int WM = BM / 2, WN = BN / 4;
    constexpr int MT = WM / 16, NT = WN / 8;
    constexpr bool CVT = (MODE == M_FRONT || MODE == M_PREP);

    const int tid = threadIdx.x, lane = tid & 31, wid = tid >> 5;
    const int wm = (wid & 1) * WM, wn = (wid >> 1) * WN;
    const int grp = lane >> 2, thr = lane & 3;

    float acc[MT][NT][4] = {};

    auto issue = [&](int i) {
        if (i < NITER) {
            int buf = i % STAGES;
            int k0 = i * KT;
            uint32_t aA = saA + buf * ABUF * 4;
            uint32_t aB = saB + buf * BBUF * 4;
#pragma unroll
            for (int q = tid; q < BM * 16; q += 256) {          // A: BM x 64k
                int m = q >> 4, kq = (q & 15) * 4;
                cp16(aA + (m * 68 + kq) * 4, rowA<MODE>(P, m0 + m, k0 + kq, s, ks, t));
            }
            if constexpr (MODE == M_PREP) {
#pragma unroll
                for (int q = tid; q < KT * 16; q += 256) {      // B: V gather (one-time)
                    int k = q >> 4, c4 = (q & 15) * 4;
                    const float* row = (s ? P.ltV : P.lvV) + (size_t)(k0 + k) * 1024;
#pragma unroll
                    for (int j = 0; j < 4; j++) {
                        int n = n0 + c4 + j;
                        cp4(aB + (k * 72 + c4 + j) * 4, row + (n & 3) * 256 + (n >> 2));
                    }
                }
            } else {
#pragma unroll
                for (int q = tid; q < KT * 16; q += 256) {      // B: 64k x 64n
                    int k = q >> 4, n4 = (q & 15) * 4;
                    int kg = k0 + k;
                    const float* row;
                    if constexpr (MODE == M_FRONT)      row = (s ? P.fc1_w : P.fc0_w) + (size_t)kg * 256;
                    else if constexpr (MODE == M_LSTHM) row = g_wp[s] + (size_t)kg * 1024;
                    else if constexpr (MODE == M_ATT)   row = g_attw + (size_t)kg * K2D;
                    else if constexpr (MODE == M_RED)   row = g_redw[s] + (size_t)(ks * 512 + kg) * 256;
                    else                                row = g_wf[s] + (size_t)kg * 1024;
                    cp16(aB + (k * 72 + n4) * 4, row + n0 + n4);
                }
            }
        }
        cpcommit();
    };

    issue(0); issue(1);

    for (int i = 0; i < NITER; i++) {
        cpwait1();
        __syncthreads();
        const float* As = smA + (i % STAGES) * ABUF;
        const float* Bs = smB + (i % STAGES) * BBUF;
#pragma unroll
        for (int kk = 0; kk < KT; kk += 8) {
            float afr[MT][4], bfr[NT][2];
#pragma unroll
            for (int mt = 0; mt < MT; mt++) {
                int mb = wm + mt * 16;
                afr[mt][0] = As[(mb + grp) * 68 + kk + thr];
                afr[mt][1] = As[(mb + grp + 8) * 68 + kk + thr];
                afr[mt][2] = As[(mb + grp) * 68 + kk + thr + 4];
                afr[mt][3] = As[(mb + grp + 8) * 68 + kk + thr + 4];
                if constexpr (CVT) {
                    afr[mt][0] = to_tf32(afr[mt][0]); afr[mt][1] = to_tf32(afr[mt][1]);
                    afr[mt][2] = to_tf32(afr[mt][2]); afr[mt][3] = to_tf32(afr[mt][3]);
                }
            }
#pragma unroll
            for (int nt = 0; nt < NT; nt++) {
                int nb = wn + nt * 8;
                bfr[nt][0] = Bs[(kk + thr) * 72 + nb + grp];
                bfr[nt][1] = Bs[(kk + thr + 4) * 72 + nb + grp];
                if constexpr (CVT) {
                    bfr[nt][0] = to_tf32(bfr[nt][0]); bfr[nt][1] = to_tf32(bfr[nt][1]);
                }
            }
#pragma unroll
            for (int mt = 0; mt < MT; mt++)
#pragma unroll
                for (int nt = 0; nt < NT; nt++)
                    mma_tf32(acc[mt][nt], afr[mt], bfr[nt]);
        }
        issue(i + 2);
    }

    // ---- epilogue ----
    if constexpr (MODE == M_LSTHM) {
        __syncthreads();
        float* smG = smB;                 // 64 x 68 floats (dead stage buffers)
        const float* bp = s ? P.ltb : P.lvb;
#pragma unroll
        for (int mt = 0; mt < MT; mt++)
#pragma unroll
            for (int nt = 0; nt < NT; nt++)
#pragma unroll
                for (int e = 0; e < 4; e++) {
                    int m_l = wm + mt * 16 + grp + ((e >= 2) ? 8 : 0);
                    int n_l = wn + nt * 8 + 2 * thr + (e & 1);
                    int np = n0 + n_l;
                    float zv = __ldcg(&g_zzv[s][(m0 + m_l) * 1024 + np]);
                    smG[m_l * 68 + n_l] = acc[mt][nt][e] + bp[(np & 3) * 256 + (np >> 2)] + zv;
                }
        __syncthreads();
#pragma unroll
        for (int j = 0; j < 4; j++) {
            int p = tid + 256 * j;                 // 1024 (m,d) pairs
            int m_l = p & 63, dl = p >> 6;
            float4 gv = *(const float4*)&smG[m_l * 68 + dl * 4];   // f,i,o,ch
            int m = m0 + m_l, d = (n0 >> 2) + dl;
            float f = sigm(gv.x), ii = sigm(gv.y), oo = sigm(gv.z), ch = tanhf(gv.w);
            float c = f * g_c[s][m * DD + d] + ii * ch;
            g_c[s][m * DD + d] = c;
            g_h[s][m * DD + d] = to_tf32(tanhf(c) * oo);
        }
        __syncthreads();
    } else {
#pragma unroll
        for (int mt = 0; mt < MT; mt++)
#pragma unroll
            for (int nt = 0; nt < NT; nt++)
#pragma unroll
                for (int e = 0; e < 4; e++) {
                    int m = m0 + wm + mt * 16 + grp + ((e >= 2) ? 8 : 0);
                    int n = n0 + wn + nt * 8 + 2 * thr + (e & 1);
                    float v = acc[mt][nt][e];
                    if constexpr (MODE == M_FRONT)
                        g_x[s][m * DD + n] = to_tf32(v + (s ? P.fc1_b : P.fc0_b)[n]);
                    else if constexpr (MODE == M_ATT)
                        g_att[m * K2D + n] = v + P.att_b[n];
                    else if constexpr (MODE == M_RED)
                        g_rp[ks][s][m * DD + n] = v;
                    else if constexpr (MODE == M_ZZV)
                        g_zzv[s][m * 1024 + n] = v + g_bf[s][n];
                    else  // M_PREP
                        g_wf[s][m * 1024 + n] = to_tf32(v);
                }
    }
}

// ---------------- softmax + attd precompute ----------------------------------
__device__ __forceinline__ void phase_softmax(const RP& P, int bid, int tid, float* hsm) {
    __shared__ float s1[8], s2[8];
    int lane = tid & 31, w = tid >> 5;
#pragma unroll 1
    for (int rr = 0; rr < 2; rr++) {
        int m = bid * 2 + rr;
        hsm[tid]       = __ldcg(g_h[0] + m * DD + tid);
        hsm[256 + tid] = __ldcg(g_h[1] + m * DD + tid);
        __syncthreads();
        const float* row = g_att + m * K2D;
        float v[8];
        float lmax = -1e30f;
#pragma unroll
        for (int i = 0; i < 8; i++) { v[i] = __ldcg(row + tid + 256 * i); lmax = fmaxf(lmax, v[i]); }
#pragma unroll
        for (int o = 16; o; o >>= 1) lmax = fmaxf(lmax, __shfl_xor_sync(0xffffffffu, lmax, o));
        if (lane == 0) s1[w] = lmax;
        __syncthreads();
        float gmax = fmaxf(fmaxf(fmaxf(s1[0], s1[1]), fmaxf(s1[2], s1[3])),
                           fmaxf(fmaxf(s1[4], s1[5]), fmaxf(s1[6], s1[7])));
        float lsum = 0.0f;
#pragma unroll
        for (int i = 0; i < 8; i++) { v[i] = expf(v[i] - gmax); lsum += v[i]; }
#pragma unroll
        for (int o = 16; o; o >>= 1) lsum += __shfl_xor_sync(0xffffffffu, lsum, o);
        if (lane == 0) s2[w] = lsum;
        __syncthreads();
        float inv = 1.0f / (s2[0] + s2[1] + s2[2] + s2[3] + s2[4] + s2[5] + s2[6] + s2[7]);
#pragma unroll
        for (int i = 0; i < 8; i++) {
            int c = tid + 256 * i;
            int slot = c >> 9, sx = (c >> 8) & 1, d = c & 255;
            g_ad[sx][m * 1024 + slot * 256 + d] = to_tf32(v[i] * inv * hsm[sx * 256 + d]);
        }
        __syncthreads();
    }
}

// ---------------- merge RED partials + relu ----------------------------------
__device__ __forceinline__ void phase_merge(const RP& P, int bid, int tid) {
#pragma unroll
    for (int j = 0; j < 4; j++) {
        int p = bid * 256 + tid + 32768 * j;       // 131072 total
        int s = p >> 16, r = p & 65535, n = r & 255;
        float v = __ldcg(&g_rp[0][s][r]) + __ldcg(&g_rp[1][s][r])
                + (s ? P.red_t_b : P.red_v_b)[n];
        g_r[s][r] = to_tf32(fmaxf(v, 0.0f));
    }
}

// ---------------- final head -------------------------------------------------
__device__ __forceinline__ void phase_final(const RP& P, int bid, int tid, float* scr) {
    float* hrow = scr;
    float* red  = scr + 512;
#pragma unroll 1
    for (int rr = 0; rr < 2; rr++) {
        int b = bid * 2 + rr;
        hrow[tid]       = __ldcg(g_h[0] + b * DD + tid);
        hrow[256 + tid] = __ldcg(g_h[1] + b * DD + tid);
        __syncthreads();
        float acc = P.late0_b[tid];
#pragma unroll 8
        for (int k = 0; k < 512; k++) acc = fmaf(hrow[k], P.late0_w[k * DD + tid], acc);
        float w1a = P.late1_w[tid * 2 + 0], w1b = P.late1_w[tid * 2 + 1];

        red[tid] = acc * w1a;
        __syncthreads();
        for (int st = 128; st; st >>= 1) { if (tid < st) red[tid] += red[tid + st]; __syncthreads(); }
        if (tid == 0) P.out[b * 2 + 0] = red[0] + P.late1_b[0];
        __syncthreads();
        red[tid] = acc * w1b;
        __syncthreads();
        for (int st = 128; st; st >>= 1) { if (tid < st) red[tid] += red[tid + st]; __syncthreads(); }
        if (tid == 0) P.out[b * 2 + 1] = red[0] + P.late1_b[1];
        __syncthreads();
    }
}

// ---------------- prep kernels ------------------------------------------------
// permute+convert [W;U] -> g_wp; convert att_w -> g_attw, red_w -> g_redw; bf.
__global__ __launch_bounds__(256) void k_perm(RP P) {
    int tid = threadIdx.x, bidx = blockIdx.x;
    // g_wp: 2 x 512 x 1024 (gate-permuted, tf32)
    {
        int base = bidx * 2048 + tid;
#pragma unroll
        for (int j = 0; j < 8; j++) {
            int idx = base + j * 256;              // 1048576
            int s = idx >> 19, r = idx & 524287;
            int k = r >> 10, np = r & 1023;
            const float* src = (k < 256) ? (s ? P.ltW : P.lvW) : (s ? P.ltU : P.lvU);
            g_wp[s][k * 1024 + np] =
                to_tf32(src[(size_t)(k & 255) * 1024 + (np & 3) * 256 + (np >> 2)]);
        }
    }
    // g_attw: 512 x 2048 (tf32)
    {
        int base = bidx * 2048 + tid;
#pragma unroll
        for (int j = 0; j < 8; j++) {
            int idx = base + j * 256;              // 1048576
            g_attw[idx] = to_tf32(P.att_w[idx]);
        }
    }
    // g_redw: 2 x 1024 x 256 (tf32)
    {
        int base = bidx * 1024 + tid;
#pragma unroll
        for (int j = 0; j < 4; j++) {
            int idx = base + j * 256;              // 524288
            int s = idx >> 18, r = idx & 262143;
            g_redw[s][r] = to_tf32((s ? P.red_t_w : P.red_v_w)[r]);
        }
    }
    // g_bf: 2 x 1024 (fp32)
    if (bidx < 2) {
        int s = bidx;
        const float* Vs = s ? P.ltV : P.lvV;
#pragma unroll
        for (int q = 0; q < 4; q++) {
            int np = tid * 4 + q;
            int a = (np & 3) * 256 + (np >> 2);
            float acc = 0.0f;
            for (int j = 0; j < 256; j++) acc = fmaf(P.mab_b[j], Vs[j * 1024 + a], acc);
            g_bf[s][np] = acc;
        }
    }
}

__global__ __launch_bounds__(256) void k_prep(RP P) {
    __shared__ float smA[STAGES * 64 * 68];
    __shared__ float smB[STAGES * 64 * 72];
    uint32_t saA = (uint32_t)__cvta_generic_to_shared(smA);
    uint32_t saB = (uint32_t)__cvta_generic_to_shared(smB);
    gemm_pipe<M_PREP, 64, 64>(P, blockIdx.z, 0, blockIdx.y * 64, blockIdx.x * 64, 0,
                              smA, smB, saA, saB);
}

__global__ __launch_bounds__(256) void k_front(RP P) {
    __shared__ float smA[STAGES * 64 * 68];
    __shared__ float smB[STAGES * 64 * 72];
    uint32_t saA = (uint32_t)__cvta_generic_to_shared(smA);
    uint32_t saB = (uint32_t)__cvta_generic_to_shared(smB);
    gemm_pipe<M_FRONT, 64, 64>(P, blockIdx.z, 0, blockIdx.y * 64, blockIdx.x * 64, 0,
                               smA, smB, saA, saB);
}

// ---------------- persistent recurrence kernel -------------------------------
__global__ __launch_bounds__(256) void k_recur(RP P) {
    __shared__ float smA[STAGES * 64 * 68];
    __shared__ float smB[STAGES * 64 * 72];
    uint32_t saA = (uint32_t)__cvta_generic_to_shared(smA);
    uint32_t saB = (uint32_t)__cvta_generic_to_shared(smB);
    const int bid = blockIdx.x, tid = threadIdx.x;

    for (int i = bid * 256 + tid; i < BB * DD; i += NBLK * 256) {
        g_h[0][i] = 0.f; g_h[1][i] = 0.f;
        g_c[0][i] = 0.f; g_c[1][i] = 0.f;
    }
    for (int i = bid * 256 + tid; i < BB * 1024; i += NBLK * 256) {
        g_zzv[0][i] = 0.f; g_zzv[1][i] = 0.f;
    }
    gsync();

#pragma unroll 1
    for (int t = 0; t < TT; t++) {
        { // LSTHM (K=512) + fused gates + zzv add: 2s x 4m x 16n tiles 64x64
            int s = bid >> 6, r = bid & 63;
            gemm_pipe<M_LSTHM, 64, 64>(P, s, 0, (r >> 4) * 64, (r & 15) * 64, t,
                                       smA, smB, saA, saB);
        }
        gsync();
        // ATT logits: 4m x 32n tiles 64x64
        gemm_pipe<M_ATT, 64, 64>(P, 0, 0, (bid >> 5) * 64, (bid & 31) * 64, t,
                                 smA, smB, saA, saB);
        gsync();
        phase_softmax(P, bid, tid, smA);
        gsync();
        { // RED split-K: 2s x 2ks x 8m x 4n tiles 32x64 (128 blocks)
            int s = bid >> 6, ks = (bid >> 5) & 1, r = bid & 31;
            gemm_pipe<M_RED, 32, 64>(P, s, ks, (r >> 2) * 32, (r & 3) * 64, t,
                                     smA, smB, saA, saB);
        }
        gsync();
        phase_merge(P, bid, tid);
        gsync();
        if (t < TT - 1) {
            { // ZZV: 2s x 4m x 16n tiles 64x64 (K=512)
                int s = bid >> 6, r = bid & 63;
                gemm_pipe<M_ZZV, 64, 64>(P, s, 0, (r >> 4) * 64, (r & 15) * 64, t,
                                         smA, smB, saA, saB);
            }
            gsync();
        }
    }

    phase_final(P, bid, tid, smA);
}

// ---------------- launch -----------------------------------------------------
extern "C" void kernel_launch(void* const* d_in, const int* in_sizes, int n_in,
                              void* d_out, int out_size) {
    RP P;
    P.xv      = (const float*)d_in[0];
    P.xt      = (const float*)d_in[1];
    P.fc0_w   = (const float*)d_in[2];
    P.fc0_b   = (const float*)d_in[3];
    P.fc1_w   = (const float*)d_in[4];
    P.fc1_b   = (const float*)d_in[5];
    P.lvW     = (const float*)d_in[6];
    P.lvU     = (const float*)d_in[7];
    P.lvV     = (const float*)d_in[8];
    P.lvb     = (const float*)d_in[9];
    P.ltW     = (const float*)d_in[10];
    P.ltU     = (const float*)d_in[11];
    P.ltV     = (const float*)d_in[12];
    P.ltb     = (const float*)d_in[13];
    P.att_w   = (const float*)d_in[14];
    P.att_b   = (const float*)d_in[15];
    P.red_v_w = (const float*)d_in[16];
    P.red_v_b = (const float*)d_in[17];
    P.red_t_w = (const float*)d_in[18];
    P.red_t_b = (const float*)d_in[19];
    P.mab_w   = (const float*)d_in[20];
    P.mab_b   = (const float*)d_in[21];
    P.late0_w = (const float*)d_in[22];
    P.late0_b = (const float*)d_in[23];
    P.late1_w = (const float*)d_in[24];
    P.late1_b = (const float*)d_in[25];
    P.out     = (float*)d_out;

    k_perm<<<512, 256>>>(P);                   // weight permute/convert + bf
    k_prep<<<dim3(16, 8, 2), 256>>>(P);        // Wf = mab_w @ V
    k_front<<<dim3(4, 100, 2), 256>>>(P);      // frontend GEMM
    k_recur<<<NBLK, 256>>>(P);                 // persistent recurrence + head
}

// round 13
// speedup vs baseline: 1.1400x; 1.1400x over previous
#include <cuda_runtime.h>
#include <cstdint>

#define BB 256
#define TT 25
#define PRE 2048
#define DD 256
#define K2D 2048
#define NBLK 256
#define STAGES 3

// ---------------- scratch (device globals) ----------------------------------
__device__ float g_x[2][BB * TT * DD];
__device__ float g_h[2][BB * DD];
__device__ float g_c[2][BB * DD];
__device__ float g_ad[2][BB * 1024];      // attended att*h (tf32)
__device__ float g_r[2][BB * DD];         // relu'd reduction output (tf32)
__device__ float g_sp[2][2][BB * 1024];   // LSTHM partials [ks][s]
__device__ float g_ap[2][BB * K2D];       // ATT partials [ks]
__device__ float g_rp[4][2][BB * DD];     // RED partials [ks][s]
__device__ float g_zzvp[2][2][BB * 1024]; // ZZV partials [ks][s]
__device__ float g_wp[2][512 * 1024];     // permuted [W;U] (tf32)
__device__ float g_wf[2][512 * 1024];     // mab_w @ V (tf32, packed)
__device__ float g_bf[2][1024];           // mab_b @ V (packed)
__device__ float g_bpk[2][1024];          // lv/lt bias (packed)
__device__ float g_attw[512 * K2D];       // att_w (tf32)
__device__ float g_redw[2][1024 * 256];   // red_{v,t}_w (tf32)

__device__ unsigned g_leafgen[16 * 32];   // per-leaf release lines
__device__ unsigned g_leaf[16 * 32];      // per-leaf arrive counters
__device__ unsigned g_root = 0;

struct RP {
    const float *xv, *xt, *fc0_w, *fc0_b, *fc1_w, *fc1_b;
    const float *lvW, *lvU, *lvV, *lvb, *ltW, *ltU, *ltV, *ltb;
    const float *att_w, *att_b, *red_v_w, *red_v_b, *red_t_w, *red_t_b, *mab_w, *mab_b;
    const float *late0_w, *late0_b, *late1_w, *late1_b;
    float* out;
};

enum { M_FRONT = 0, M_LSTHM, M_ATT, M_RED, M_ZZV, M_PREP };

template <int MODE> __host__ __device__ constexpr int kdim() {
    return MODE == M_FRONT ? 2048 : 256;   // recurrence GEMMs are split-K 256
}

// ---------------- grid sync (16 leaves x 16 blocks, broadcast release) -------
__device__ __forceinline__ void gsync() {
    __threadfence();
    __syncthreads();
    if (threadIdx.x == 0) {
        int lf = blockIdx.x >> 4;
        volatile unsigned* lg = &g_leafgen[lf * 32];
        unsigned gen = *lg;
        if (atomicAdd(&g_leaf[lf * 32], 1u) == 15u) {
            g_leaf[lf * 32] = 0;
            __threadfence();
            if (atomicAdd(&g_root, 1u) == 15u) {
                g_root = 0;
                __threadfence();
#pragma unroll
                for (int j = 0; j < 16; j++)
                    ((volatile unsigned*)g_leafgen)[j * 32] = gen + 1;
            } else {
                while (*lg == gen) {}
            }
        } else {
            while (*lg == gen) {}
        }
    }
    __syncthreads();
}

// ---------------- cp.async / tf32 helpers ------------------------------------
__device__ __forceinline__ void cp16(uint32_t dst, const void* src) {
    asm volatile("cp.async.cg.shared.global [%0], [%1], 16;" :: "r"(dst), "l"(src));
}
__device__ __forceinline__ void cp4(uint32_t dst, const void* src) {
    asm volatile("cp.async.ca.shared.global [%0], [%1], 4;" :: "r"(dst), "l"(src));
}
__device__ __forceinline__ void cpcommit() { asm volatile("cp.async.commit_group;"); }
__device__ __forceinline__ void cpwait1()  { asm volatile("cp.async.wait_group 1;"); }

__device__ __forceinline__ float to_tf32(float x) {
    asm("cvt.rna.tf32.f32 %0, %0;" : "+f"(x));
    return x;
}
__device__ __forceinline__ float sigm(float x) { return 1.0f / (1.0f + expf(-x)); }

__device__ __forceinline__ void mma_tf32(float* acc, const float* a, const float* b) {
    asm volatile(
        "mma.sync.aligned.m16n8k8.row.col.f32.tf32.tf32.f32 "
        "{%0,%1,%2,%3}, {%4,%5,%6,%7}, {%8,%9}, {%0,%1,%2,%3};\n"
        : "+f"(acc[0]), "+f"(acc[1]), "+f"(acc[2]), "+f"(acc[3])
        : "r"(__float_as_uint(a[0])), "r"(__float_as_uint(a[1])),
          "r"(__float_as_uint(a[2])), "r"(__float_as_uint(a[3])),
          "r"(__float_as_uint(b[0])), "r"(__float_as_uint(b[1])));
}

// ---------------- A-row pointer (k local to split) ---------------------------
template <int MODE>
__device__ __forceinline__ const float* rowA(const RP& P, int m, int k, int s, int ks, int t) {
    if constexpr (MODE == M_FRONT)      return (s ? P.xt : P.xv) + (size_t)m * PRE + k;
    else if constexpr (MODE == M_LSTHM)
        return ks ? g_h[s] + m * DD + k : g_x[s] + (m * TT + t) * DD + k;
    else if constexpr (MODE == M_ATT)   return g_h[ks] + m * DD + k;
    else if constexpr (MODE == M_RED)   return g_ad[s] + m * 1024 + ks * 256 + k;
    else if constexpr (MODE == M_ZZV)   return g_r[ks] + m * DD + k;
    else                                return P.mab_w + (size_t)m * 256 + k;  // M_PREP
}

// ---------------- pipelined tf32 MMA GEMM (256 thr, KT=32, 3 stages) ---------
template <int MODE, int BM, int BN>
__device__ __forceinline__ void gemm_pipe(const RP& P, int s, int ks, int m0, int n0, int t,
                                          float* smA, float* smB,
                                          uint32_t saA, uint32_t saB) {
    constexpr int KD = kdim<MODE>();
    constexpr int KT = 32;
    constexpr int NITER = KD / KT;
    constexpr int ABUF = BM * 36;
    constexpr int BBUF = KT * 72;
    constexpr int WM = BM / 2, WN = BN / 4;
    constexpr int MT = WM / 16, NT = WN / 8;
    constexpr bool CVT = (MODE == M_FRONT || MODE == M_PREP);

    const int koff = CVT ? 0 : ks * 256;
    const int tid = threadIdx.x, lane = tid & 31, wid = tid >> 5;
    const int wm = (wid & 1) * WM, wn = (wid >> 1) * WN;
    const int grp = lane >> 2, thr = lane & 3;

    float acc[MT][NT][4] = {};

    auto issue = [&](int i) {
        if (i < NITER) {
            int buf = i % STAGES;
            int k0 = i * KT;
            uint32_t aA = saA + buf * ABUF * 4;
            uint32_t aB = saB + buf * BBUF * 4;
#pragma unroll
            for (int q = tid; q < BM * 8; q += 256) {           // A: BM x 32k
                int m = q >> 3, kq = (q & 7) * 4;
                cp16(aA + (m * 36 + kq) * 4, rowA<MODE>(P, m0 + m, k0 + kq, s, ks, t));
            }
            if constexpr (MODE == M_PREP) {
#pragma unroll
                for (int q = tid; q < 512; q += 256) {          // B: V gather (one-time)
                    int k = q >> 4, c4 = (q & 15) * 4;
                    const float* row = (s ? P.ltV : P.lvV) + (size_t)(k0 + k) * 1024;
#pragma unroll
                    for (int j = 0; j < 4; j++) {
                        int n = n0 + c4 + j;
                        cp4(aB + (k * 72 + c4 + j) * 4, row + (n & 3) * 256 + (n >> 2));
                    }
                }
            } else {
#pragma unroll
                for (int q = tid; q < 512; q += 256) {          // B: 32k x 64n
                    int k = q >> 4, n4 = (q & 15) * 4;
                    int kg = koff + k0 + k;
                    const float* row;
                    if constexpr (MODE == M_FRONT)      row = (s ? P.fc1_w : P.fc0_w) + (size_t)kg * 256;
                    else if constexpr (MODE == M_LSTHM) row = g_wp[s] + (size_t)kg * 1024;
                    else if constexpr (MODE == M_ATT)   row = g_attw + (size_t)kg * K2D;
                    else if constexpr (MODE == M_RED)   row = g_redw[s] + (size_t)kg * 256;
                    else                                row = g_wf[s] + (size_t)kg * 1024;
                    cp16(aB + (k * 72 + n4) * 4, row + n0 + n4);
                }
            }
        }
        cpcommit();
    };

    issue(0); issue(1);

    for (int i = 0; i < NITER; i++) {
        cpwait1();
        __syncthreads();
        const float* As = smA + (i % STAGES) * ABUF;
        const float* Bs = smB + (i % STAGES) * BBUF;
#pragma unroll
        for (int kk = 0; kk < KT; kk += 8) {
            float afr[MT][4], bfr[NT][2];
#pragma unroll
            for (int mt = 0; mt < MT; mt++) {
                int mb = wm + mt * 16;
                afr[mt][0] = As[(mb + grp) * 36 + kk + thr];
                afr[mt][1] = As[(mb + grp + 8) * 36 + kk + thr];
                afr[mt][2] = As[(mb + grp) * 36 + kk + thr + 4];
                afr[mt][3] = As[(mb + grp + 8) * 36 + kk + thr + 4];
                if constexpr (CVT) {
                    afr[mt][0] = to_tf32(afr[mt][0]); afr[mt][1] = to_tf32(afr[mt][1]);
                    afr[mt][2] = to_tf32(afr[mt][2]); afr[mt][3] = to_tf32(afr[mt][3]);
                }
            }
#pragma unroll
            for (int nt = 0; nt < NT; nt++) {
                int nb = wn + nt * 8;
                bfr[nt][0] = Bs[(kk + thr) * 72 + nb + grp];
                bfr[nt][1] = Bs[(kk + thr + 4) * 72 + nb + grp];
                if constexpr (CVT) {
                    bfr[nt][0] = to_tf32(bfr[nt][0]); bfr[nt][1] = to_tf32(bfr[nt][1]);
                }
            }
#pragma unroll
            for (int mt = 0; mt < MT; mt++)
#pragma unroll
                for (int nt = 0; nt < NT; nt++)
                    mma_tf32(acc[mt][nt], afr[mt], bfr[nt]);
        }
        issue(i + 2);
    }

    // ---- epilogue: write raw partials (recurrence) or finished (front/prep) --
#pragma unroll
    for (int mt = 0; mt < MT; mt++)
#pragma unroll
        for (int nt = 0; nt < NT; nt++)
#pragma unroll
            for (int e = 0; e < 4; e++) {
                int m = m0 + wm + mt * 16 + grp + ((e >= 2) ? 8 : 0);
                int n = n0 + wn + nt * 8 + 2 * thr + (e & 1);
                float v = acc[mt][nt][e];
                if constexpr (MODE == M_FRONT)
                    g_x[s][m * DD + n] = to_tf32(v + (s ? P.fc1_b : P.fc0_b)[n]);
                else if constexpr (MODE == M_LSTHM)
                    g_sp[ks][s][m * 1024 + n] = v;
                else if constexpr (MODE == M_ATT)
                    g_ap[ks][m * K2D + n] = v;
                else if constexpr (MODE == M_RED)
                    g_rp[ks][s][m * DD + n] = v;
                else if constexpr (MODE == M_ZZV)
                    g_zzvp[ks][s][m * 1024 + n] = v;
                else  // M_PREP
                    g_wf[s][m * 1024 + n] = to_tf32(v);
            }
}

// ---------------- gates: merge LSTHM partials + zzv, update c,h --------------
__device__ __forceinline__ void phase_gates(const RP& P, int bid, int tid, int t) {
#pragma unroll
    for (int j = 0; j < 2; j++) {
        int idx = bid * 256 + tid + j * 65536;     // 131072 (s,m,d) triples
        int s = idx >> 16, r = idx & 65535;
        int m = r >> 8, d = r & 255;
        int o4 = m * 1024 + d * 4;
        float4 p0 = __ldcg((const float4*)(g_sp[0][s] + o4));
        float4 p1 = __ldcg((const float4*)(g_sp[1][s] + o4));
        float4 z0 = __ldcg((const float4*)(g_zzvp[0][s] + o4));
        float4 z1 = __ldcg((const float4*)(g_zzvp[1][s] + o4));
        float4 bb = *(const float4*)(g_bpk[s] + d * 4);
        float fx = p0.x + p1.x + z0.x + z1.x + bb.x;
        float fy = p0.y + p1.y + z0.y + z1.y + bb.y;
        float fz = p0.z + p1.z + z0.z + z1.z + bb.z;
        float fw = p0.w + p1.w + z0.w + z1.w + bb.w;
        if (t > 0) {
            float4 bf = *(const float4*)(g_bf[s] + d * 4);
            fx += bf.x; fy += bf.y; fz += bf.z; fw += bf.w;
        }
        float f = sigm(fx), ii = sigm(fy), oo = sigm(fz), ch = tanhf(fw);
        float c = f * g_c[s][r] + ii * ch;
        g_c[s][r] = c;
        g_h[s][r] = to_tf32(tanhf(c) * oo);
    }
}

// ---------------- softmax (1 row/block): merge ATT partials + attd -----------
__device__ __forceinline__ void phase_softmax(const RP& P, int bid, int tid, float* hsm) {
    __shared__ float s1[8], s2[8];
    int lane = tid & 31, w = tid >> 5;
    int m = bid;
    hsm[tid]       = __ldcg(g_h[0] + m * DD + tid);
    hsm[256 + tid] = __ldcg(g_h[1] + m * DD + tid);
    __syncthreads();
    float v[8];
    float lmax = -1e30f;
#pragma unroll
    for (int i = 0; i < 8; i++) {
        int c = tid + 256 * i;
        v[i] = __ldcg(g_ap[0] + m * K2D + c) + __ldcg(g_ap[1] + m * K2D + c) + P.att_b[c];
        lmax = fmaxf(lmax, v[i]);
    }
#pragma unroll
    for (int o = 16; o; o >>= 1) lmax = fmaxf(lmax, __shfl_xor_sync(0xffffffffu, lmax, o));
    if (lane == 0) s1[w] = lmax;
    __syncthreads();
    float gmax = fmaxf(fmaxf(fmaxf(s1[0], s1[1]), fmaxf(s1[2], s1[3])),
                       fmaxf(fmaxf(s1[4], s1[5]), fmaxf(s1[6], s1[7])));
    float lsum = 0.0f;
#pragma unroll
    for (int i = 0; i < 8; i++) { v[i] = expf(v[i] - gmax); lsum += v[i]; }
#pragma unroll
    for (int o = 16; o; o >>= 1) lsum += __shfl_xor_sync(0xffffffffu, lsum, o);
    if (lane == 0) s2[w] = lsum;
    __syncthreads();
    float inv = 1.0f / (s2[0] + s2[1] + s2[2] + s2[3] + s2[4] + s2[5] + s2[6] + s2[7]);
#pragma unroll
    for (int i = 0; i < 8; i++) {
        int c = tid + 256 * i;
        int slot = c >> 9, sx = (c >> 8) & 1, d = c & 255;
        g_ad[sx][m * 1024 + slot * 256 + d] = to_tf32(v[i] * inv * hsm[sx * 256 + d]);
    }
    __syncthreads();
}

// ---------------- merge RED partials + relu ----------------------------------
__device__ __forceinline__ void phase_merge(const RP& P, int bid, int tid) {
#pragma unroll
    for (int j = 0; j < 2; j++) {
        int idx = bid * 256 + tid + j * 65536;     // 131072 outputs
        int s = idx >> 16, r = idx & 65535, n = r & 255;
        float v = __ldcg(&g_rp[0][s][r]) + __ldcg(&g_rp[1][s][r])
                + __ldcg(&g_rp[2][s][r]) + __ldcg(&g_rp[3][s][r])
                + (s ? P.red_t_b : P.red_v_b)[n];
        g_r[s][r] = to_tf32(fmaxf(v, 0.0f));
    }
}

// ---------------- final head (1 row/block) -----------------------------------
__device__ __forceinline__ void phase_final(const RP& P, int bid, int tid, float* scr) {
    float* hrow = scr;
    float* red  = scr + 512;
    int b = bid;
    hrow[tid]       = __ldcg(g_h[0] + b * DD + tid);
    hrow[256 + tid] = __ldcg(g_h[1] + b * DD + tid);
    __syncthreads();
    float acc = P.late0_b[tid];
#pragma unroll 8
    for (int k = 0; k < 512; k++) acc = fmaf(hrow[k], P.late0_w[k * DD + tid], acc);
    float w1a = P.late1_w[tid * 2 + 0], w1b = P.late1_w[tid * 2 + 1];

    red[tid] = acc * w1a;
    __syncthreads();
    for (int st = 128; st; st >>= 1) { if (tid < st) red[tid] += red[tid + st]; __syncthreads(); }
    if (tid == 0) P.out[b * 2 + 0] = red[0] + P.late1_b[0];
    __syncthreads();
    red[tid] = acc * w1b;
    __syncthreads();
    for (int st = 128; st; st >>= 1) { if (tid < st) red[tid] += red[tid + st]; __syncthreads(); }
    if (tid == 0) P.out[b * 2 + 1] = red[0] + P.late1_b[1];
}

// ---------------- prep kernels ------------------------------------------------
__global__ __launch_bounds__(256) void k_perm(RP P) {
    int tid = threadIdx.x, bidx = blockIdx.x;
    // g_wp: 2 x 512 x 1024 (gate-permuted, tf32)
    {
        int base = bidx * 2048 + tid;
#pragma unroll
        for (int j = 0; j < 8; j++) {
            int idx = base + j * 256;              // 1048576
            int s = idx >> 19, r = idx & 524287;
            int k = r >> 10, np = r & 1023;
            const float* src = (k < 256) ? (s ? P.ltW : P.lvW) : (s ? P.ltU : P.lvU);
            g_wp[s][k * 1024 + np] =
                to_tf32(src[(size_t)(k & 255) * 1024 + (np & 3) * 256 + (np >> 2)]);
        }
    }
    // g_attw: 512 x 2048 (tf32)
    {
        int base = bidx * 2048 + tid;
#pragma unroll
        for (int j = 0; j < 8; j++) {
            int idx = base + j * 256;
            g_attw[idx] = to_tf32(P.att_w[idx]);
        }
    }
    // g_redw: 2 x 1024 x 256 (tf32)
    {
        int base = bidx * 1024 + tid;
#pragma unroll
        for (int j = 0; j < 4; j++) {
            int idx = base + j * 256;
            int s = idx >> 18, r = idx & 262143;
            g_redw[s][r] = to_tf32((s ? P.red_t_w : P.red_v_w)[r]);
        }
    }
    // g_bf, g_bpk: 2 x 1024 each
    if (bidx < 2) {
        int s = bidx;
        const float* Vs = s ? P.ltV : P.lvV;
        const float* bp = s ? P.ltb : P.lvb;
#pragma unroll
        for (int q = 0; q < 4; q++) {
            int np = tid * 4 + q;
            int a = (np & 3) * 256 + (np >> 2);
            float acc = 0.0f;
            for (int j = 0; j < 256; j++) acc = fmaf(P.mab_b[j], Vs[j * 1024 + a], acc);
            g_bf[s][np] = acc;
            g_bpk[s][np] = bp[a];
        }
    }
}

__global__ __launch_bounds__(256, 2) void k_prep(RP P) {
    __shared__ float smA[STAGES * 64 * 36];
    __shared__ float smB[STAGES * 32 * 72];
    uint32_t saA = (uint32_t)__cvta_generic_to_shared(smA);
    uint32_t saB = (uint32_t)__cvta_generic_to_shared(smB);
    gemm_pipe<M_PREP, 64, 64>(P, blockIdx.z, 0, blockIdx.y * 64, blockIdx.x * 64, 0,
                              smA, smB, saA, saB);
}

__global__ __launch_bounds__(256, 2) void k_front(RP P) {
    __shared__ float smA[STAGES * 64 * 36];
    __shared__ float smB[STAGES * 32 * 72];
    uint32_t saA = (uint32_t)__cvta_generic_to_shared(smA);
    uint32_t saB = (uint32_t)__cvta_generic_to_shared(smB);
    gemm_pipe<M_FRONT, 64, 64>(P, blockIdx.z, 0, blockIdx.y * 64, blockIdx.x * 64, 0,
                               smA, smB, saA, saB);
}

// ---------------- persistent recurrence kernel (256 blocks, 2/SM) ------------
__global__ __launch_bounds__(256, 2) void k_recur(RP P) {
    __shared__ float smA[STAGES * 64 * 36];
    __shared__ float smB[STAGES * 32 * 72];
    uint32_t saA = (uint32_t)__cvta_generic_to_shared(smA);
    uint32_t saB = (uint32_t)__cvta_generic_to_shared(smB);
    const int bid = blockIdx.x, tid = threadIdx.x;

    for (int i = bid * 256 + tid; i < BB * DD; i += NBLK * 256) {
        g_h[0][i] = 0.f; g_h[1][i] = 0.f;
        g_c[0][i] = 0.f; g_c[1][i] = 0.f;
    }
    for (int i = bid * 256 + tid; i < BB * 1024; i += NBLK * 256) {
        g_zzvp[0][0][i] = 0.f; g_zzvp[0][1][i] = 0.f;
        g_zzvp[1][0][i] = 0.f; g_zzvp[1][1][i] = 0.f;
    }
    gsync();

#pragma unroll 1
    for (int t = 0; t < TT; t++) {
        { // LSTHM split-K: 2ks x 2s x 4m x 16n tiles 64x64 (256 blocks)
            int ks = bid >> 7, s = (bid >> 6) & 1, r = bid & 63;
            gemm_pipe<M_LSTHM, 64, 64>(P, s, ks, (r >> 4) * 64, (r & 15) * 64, t,
                                       smA, smB, saA, saB);
        }
        gsync();
        phase_gates(P, bid, tid, t);
        gsync();
        { // ATT split-K: 2ks x 4m x 32n tiles 64x64 (256 blocks)
            int ks = bid >> 7, r = bid & 127;
            gemm_pipe<M_ATT, 64, 64>(P, 0, ks, (r >> 5) * 64, (r & 31) * 64, t,
                                     smA, smB, saA, saB);
        }
        gsync();
        phase_softmax(P, bid, tid, smA);
        gsync();
        { // RED split-K: 2s x 4ks x 8m x 4n tiles 32x64 (256 blocks)
            int s = bid >> 7, ks = (bid >> 5) & 3, r = bid & 31;
            gemm_pipe<M_RED, 32, 64>(P, s, ks, (r >> 2) * 32, (r & 3) * 64, t,
                                     smA, smB, saA, saB);
        }
        gsync();
        phase_merge(P, bid, tid);
        gsync();
        if (t < TT - 1) {
            { // ZZV split-K: 2ks x 2s x 4m x 16n tiles 64x64 (256 blocks)
                int ks = bid >> 7, s = (bid >> 6) & 1, r = bid & 63;
                gemm_pipe<M_ZZV, 64, 64>(P, s, ks, (r >> 4) * 64, (r & 15) * 64, t,
                                         smA, smB, saA, saB);
            }
            gsync();
        }
    }

    phase_final(P, bid, tid, smA);
}

// ---------------- launch -----------------------------------------------------
extern "C" void kernel_launch(void* const* d_in, const int* in_sizes, int n_in,
                              void* d_out, int out_size) {
    RP P;
    P.xv      = (const float*)d_in[0];
    P.xt      = (const float*)d_in[1];
    P.fc0_w   = (const float*)d_in[2];
    P.fc0_b   = (const float*)d_in[3];
    P.fc1_w   = (const float*)d_in[4];
    P.fc1_b   = (const float*)d_in[5];
    P.lvW     = (const float*)d_in[6];
    P.lvU     = (const float*)d_in[7];
    P.lvV     = (const float*)d_in[8];
    P.lvb     = (const float*)d_in[9];
    P.ltW     = (const float*)d_in[10];
    P.ltU     = (const float*)d_in[11];
    P.ltV     = (const float*)d_in[12];
    P.ltb     = (const float*)d_in[13];
    P.att_w   = (const float*)d_in[14];
    P.att_b   = (const float*)d_in[15];
    P.red_v_w = (const float*)d_in[16];
    P.red_v_b = (const float*)d_in[17];
    P.red_t_w = (const float*)d_in[18];
    P.red_t_b = (const float*)d_in[19];
    P.mab_w   = (const float*)d_in[20];
    P.mab_b   = (const float*)d_in[21];
    P.late0_w = (const float*)d_in[22];
    P.late0_b = (const float*)d_in[23];
    P.late1_w = (const float*)d_in[24];
    P.late1_b = (const float*)d_in[25];
    P.out     = (float*)d_out;

    k_perm<<<512, 256>>>(P);                   // weight permute/convert + biases
    k_prep<<<dim3(16, 8, 2), 256>>>(P);        // Wf = mab_w @ V
    k_front<<<dim3(4, 100, 2), 256>>>(P);      // frontend GEMM
    k_recur<<<NBLK, 256>>>(P);                 // persistent recurrence + head
}

// round 15
// speedup vs baseline: 1.2164x; 1.0671x over previous
#include <cuda_runtime.h>
#include <cstdint>

#define BB 256
#define TT 25
#define PRE 2048
#define DD 256
#define K2D 2048
#define NBLK 256
#define STAGES 3

// ---------------- scratch (device globals) ----------------------------------
__device__ float g_x[2][BB * TT * DD];
__device__ float g_h[2][BB * DD];
__device__ float g_c[2][BB * DD];
__device__ float g_ad[2][BB * 1024];      // attended att*h (tf32)
__device__ float g_r[2][BB * DD];         // relu'd reduction output (tf32)
__device__ float g_sp[2][2][BB * 1024];   // LSTHM partials [ks][s]
__device__ float g_ap[2][BB * K2D];       // ATT partials [ks]
__device__ float g_rp[4][2][BB * DD];     // RED partials [ks][s]
__device__ float g_wp[2][512 * 1024];     // permuted [W;U] (tf32)
__device__ float g_wf[2][512 * 1024];     // mab_w @ V (tf32, packed)
__device__ float g_bf[2][1024];           // mab_b @ V (packed)
__device__ float g_bpk[2][1024];          // lv/lt bias (packed)
__device__ float g_attw[512 * K2D];       // att_w (tf32)
__device__ float g_redw[2][1024 * 256];   // red_{v,t}_w (tf32)

__device__ unsigned g_leafgen[16 * 32];   // per-leaf release lines
__device__ unsigned g_leaf[16 * 32];      // per-leaf arrive counters
__device__ unsigned g_root = 0;

struct RP {
    const float *xv, *xt, *fc0_w, *fc0_b, *fc1_w, *fc1_b;
    const float *lvW, *lvU, *lvV, *lvb, *ltW, *ltU, *ltV, *ltb;
    const float *att_w, *att_b, *red_v_w, *red_v_b, *red_t_w, *red_t_b, *mab_w, *mab_b;
    const float *late0_w, *late0_b, *late1_w, *late1_b;
    float* out;
};

enum { M_FRONT = 0, M_LSTHM, M_ATT, M_RED, M_PREP };

template <int MODE> __host__ __device__ constexpr int kdim() {
    return MODE == M_FRONT ? 2048 : MODE == M_LSTHM ? 512 : 256;
}

// ---------------- grid sync (16 leaves x 16 blocks, broadcast release) -------
__device__ __forceinline__ void gsync() {
    __threadfence();
    __syncthreads();
    if (threadIdx.x == 0) {
        int lf = blockIdx.x >> 4;
        volatile unsigned* lg = &g_leafgen[lf * 32];
        unsigned gen = *lg;
        if (atomicAdd(&g_leaf[lf * 32], 1u) == 15u) {
            g_leaf[lf * 32] = 0;
            __threadfence();
            if (atomicAdd(&g_root, 1u) == 15u) {
                g_root = 0;
                __threadfence();
#pragma unroll
                for (int j = 0; j < 16; j++)
                    ((volatile unsigned*)g_leafgen)[j * 32] = gen + 1;
            } else {
                while (*lg == gen) {}
            }
        } else {
            while (*lg == gen) {}
        }
    }
    __syncthreads();
}

// ---------------- cp.async / tf32 helpers ------------------------------------
__device__ __forceinline__ void cp16(uint32_t dst, const void* src) {
    asm volatile("cp.async.cg.shared.global [%0], [%1], 16;" :: "r"(dst), "l"(src));
}
__device__ __forceinline__ void cp4(uint32_t dst, const void* src) {
    asm volatile("cp.async.ca.shared.global [%0], [%1], 4;" :: "r"(dst), "l"(src));
}
__device__ __forceinline__ void cpcommit() { asm volatile("cp.async.commit_group;"); }
__device__ __forceinline__ void cpwait1()  { asm volatile("cp.async.wait_group 1;"); }

__device__ __forceinline__ float to_tf32(float x) {
    asm("cvt.rna.tf32.f32 %0, %0;" : "+f"(x));
    return x;
}
__device__ __forceinline__ float sigm(float x) { return 1.0f / (1.0f + expf(-x)); }

__device__ __forceinline__ void mma_tf32(float* acc, const float* a, const float* b) {
    asm volatile(
        "mma.sync.aligned.m16n8k8.row.col.f32.tf32.tf32.f32 "
        "{%0,%1,%2,%3}, {%4,%5,%6,%7}, {%8,%9}, {%0,%1,%2,%3};\n"
        : "+f"(acc[0]), "+f"(acc[1]), "+f"(acc[2]), "+f"(acc[3])
        : "r"(__float_as_uint(a[0])), "r"(__float_as_uint(a[1])),
          "r"(__float_as_uint(a[2])), "r"(__float_as_uint(a[3])),
          "r"(__float_as_uint(b[0])), "r"(__float_as_uint(b[1])));
}

// ---------------- A-row pointer (k local to split) ---------------------------
template <int MODE>
__device__ __forceinline__ const float* rowA(const RP& P, int m, int k, int s, int ks, int t) {
    if constexpr (MODE == M_FRONT)      return (s ? P.xt : P.xv) + (size_t)m * PRE + k;
    else if constexpr (MODE == M_LSTHM) {
        // fused [x,h | r0,r1] @ [Wp | Wf], K=1024 split in two 512 halves
        if (ks == 0) return (k < DD) ? g_x[s] + (m * TT + t) * DD + k
                                     : g_h[s] + m * DD + (k - DD);
        else         return (k < DD) ? g_r[0] + m * DD + k
                                     : g_r[1] + m * DD + (k - DD);
    }
    else if constexpr (MODE == M_ATT)   return g_h[ks] + m * DD + k;
    else if constexpr (MODE == M_RED)   return g_ad[s] + m * 1024 + ks * 256 + k;
    else                                return P.mab_w + (size_t)m * 256 + k;  // M_PREP
}

// ---------------- pipelined tf32 MMA GEMM (256 thr, KT=32, 3 stages) ---------
template <int MODE, int BM, int BN>
__device__ __forceinline__ void gemm_pipe(const RP& P, int s, int ks, int m0, int n0, int t,
                                          float* smA, float* smB,
                                          uint32_t saA, uint32_t saB) {
    constexpr int KD = kdim<MODE>();
    constexpr int KT = 32;
    constexpr int NITER = KD / KT;
    constexpr int ABUF = BM * 36;
    constexpr int BBUF = KT * 72;
    constexpr int WM = BM / 2, WN = BN / 4;
    constexpr int MT = WM / 16, NT = WN / 8;
    constexpr bool CVT = (MODE == M_FRONT || MODE == M_PREP);

    const int koff = (MODE == M_ATT || MODE == M_RED) ? ks * 256 : 0;
    const int tid = threadIdx.x, lane = tid & 31, wid = tid >> 5;
    const int wm = (wid & 1) * WM, wn = (wid >> 1) * WN;
    const int grp = lane >> 2, thr = lane & 3;

    float acc[MT][NT][4] = {};

    auto issue = [&](int i) {
        if (i < NITER) {
            int buf = i % STAGES;
            int k0 = i * KT;
            uint32_t aA = saA + buf * ABUF * 4;
            uint32_t aB = saB + buf * BBUF * 4;
#pragma unroll
            for (int q = tid; q < BM * 8; q += 256) {           // A: BM x 32k
                int m = q >> 3, kq = (q & 7) * 4;
                cp16(aA + (m * 36 + kq) * 4, rowA<MODE>(P, m0 + m, k0 + kq, s, ks, t));
            }
            if constexpr (MODE == M_PREP) {
#pragma unroll
                for (int q = tid; q < 512; q += 256) {          // B: V gather (one-time)
                    int k = q >> 4, c4 = (q & 15) * 4;
                    const float* row = (s ? P.ltV : P.lvV) + (size_t)(k0 + k) * 1024;
#pragma unroll
                    for (int j = 0; j < 4; j++) {
                        int n = n0 + c4 + j;
                        cp4(aB + (k * 72 + c4 + j) * 4, row + (n & 3) * 256 + (n >> 2));
                    }
                }
            } else {
#pragma unroll
                for (int q = tid; q < 512; q += 256) {          // B: 32k x 64n
                    int k = q >> 4, n4 = (q & 15) * 4;
                    int kg = koff + k0 + k;
                    const float* row;
                    if constexpr (MODE == M_FRONT)      row = (s ? P.fc1_w : P.fc0_w) + (size_t)kg * 256;
                    else if constexpr (MODE == M_LSTHM) row = (ks ? g_wf[s] : g_wp[s]) + (size_t)kg * 1024;
                    else if constexpr (MODE == M_ATT)   row = g_attw + (size_t)kg * K2D;
                    else                                row = g_redw[s] + (size_t)kg * 256;
                    cp16(aB + (k * 72 + n4) * 4, row + n0 + n4);
                }
            }
        }
        cpcommit();
    };

    issue(0); issue(1);

    for (int i = 0; i < NITER; i++) {
        cpwait1();
        __syncthreads();
        const float* As = smA + (i % STAGES) * ABUF;
        const float* Bs = smB + (i % STAGES) * BBUF;
#pragma unroll
        for (int kk = 0; kk < KT; kk += 8) {
            float afr[MT][4], bfr[NT][2];
#pragma unroll
            for (int mt = 0; mt < MT; mt++) {
                int mb = wm + mt * 16;
                afr[mt][0] = As[(mb + grp) * 36 + kk + thr];
                afr[mt][1] = As[(mb + grp + 8) * 36 + kk + thr];
                afr[mt][2] = As[(mb + grp) * 36 + kk + thr + 4];
                afr[mt][3] = As[(mb + grp + 8) * 36 + kk + thr + 4];
                if constexpr (CVT) {
                    afr[mt][0] = to_tf32(afr[mt][0]); afr[mt][1] = to_tf32(afr[mt][1]);
                    afr[mt][2] = to_tf32(afr[mt][2]); afr[mt][3] = to_tf32(afr[mt][3]);
                }
            }
#pragma unroll
            for (int nt = 0; nt < NT; nt++) {
                int nb = wn + nt * 8;
                bfr[nt][0] = Bs[(kk + thr) * 72 + nb + grp];
                bfr[nt][1] = Bs[(kk + thr + 4) * 72 + nb + grp];
                if constexpr (CVT) {
                    bfr[nt][0] = to_tf32(bfr[nt][0]); bfr[nt][1] = to_tf32(bfr[nt][1]);
                }
            }
#pragma unroll
            for (int mt = 0; mt < MT; mt++)
#pragma unroll
                for (int nt = 0; nt < NT; nt++)
                    mma_tf32(acc[mt][nt], afr[mt], bfr[nt]);
        }
        issue(i + 2);
    }

    // ---- epilogue ----
#pragma unroll
    for (int mt = 0; mt < MT; mt++)
#pragma unroll
        for (int nt = 0; nt < NT; nt++)
#pragma unroll
            for (int e = 0; e < 4; e++) {
                int m = m0 + wm + mt * 16 + grp + ((e >= 2) ? 8 : 0);
                int n = n0 + wn + nt * 8 + 2 * thr + (e & 1);
                float v = acc[mt][nt][e];
                if constexpr (MODE == M_FRONT)
                    g_x[s][m * DD + n] = to_tf32(v + (s ? P.fc1_b : P.fc0_b)[n]);
                else if constexpr (MODE == M_LSTHM)
                    g_sp[ks][s][m * 1024 + n] = v;
                else if constexpr (MODE == M_ATT)
                    g_ap[ks][m * K2D + n] = v;
                else if constexpr (MODE == M_RED)
                    g_rp[ks][s][m * DD + n] = v;
                else  // M_PREP
                    g_wf[s][m * 1024 + n] = to_tf32(v);
            }
}

// ---------------- gates: merge 2 LSTHM partials, update c,h ------------------
__device__ __forceinline__ void phase_gates(const RP& P, int bid, int tid, int t) {
#pragma unroll
    for (int j = 0; j < 2; j++) {
        int idx = bid * 256 + tid + j * 65536;     // 131072 (s,m,d) triples
        int s = idx >> 16, r = idx & 65535;
        int m = r >> 8, d = r & 255;
        int o4 = m * 1024 + d * 4;
        float4 p0 = __ldcg((const float4*)(g_sp[0][s] + o4));
        float4 p1 = __ldcg((const float4*)(g_sp[1][s] + o4));
        float4 bb = *(const float4*)(g_bpk[s] + d * 4);
        float fx = p0.x + p1.x + bb.x;
        float fy = p0.y + p1.y + bb.y;
        float fz = p0.z + p1.z + bb.z;
        float fw = p0.w + p1.w + bb.w;
        if (t > 0) {
            float4 bf = *(const float4*)(g_bf[s] + d * 4);
            fx += bf.x; fy += bf.y; fz += bf.z; fw += bf.w;
        }
        float f = sigm(fx), ii = sigm(fy), oo = sigm(fz), ch = tanhf(fw);
        float c = f * g_c[s][r] + ii * ch;
        g_c[s][r] = c;
        g_h[s][r] = to_tf32(tanhf(c) * oo);
    }
}

// ---------------- softmax (1 row/block): merge ATT partials + attd -----------
__device__ __forceinline__ void phase_softmax(const RP& P, int bid, int tid, float* hsm) {
    __shared__ float s1[8], s2[8];
    int lane = tid & 31, w = tid >> 5;
    int m = bid;
    hsm[tid]       = __ldcg(g_h[0] + m * DD + tid);
    hsm[256 + tid] = __ldcg(g_h[1] + m * DD + tid);
    __syncthreads();
    float v[8];
    float lmax = -1e30f;
#pragma unroll
    for (int i = 0; i < 8; i++) {
        int c = tid + 256 * i;
        v[i] = __ldcg(g_ap[0] + m * K2D + c) + __ldcg(g_ap[1] + m * K2D + c) + P.att_b[c];
        lmax = fmaxf(lmax, v[i]);
    }
#pragma unroll
    for (int o = 16; o; o >>= 1) lmax = fmaxf(lmax, __shfl_xor_sync(0xffffffffu, lmax, o));
    if (lane == 0) s1[w] = lmax;
    __syncthreads();
    float gmax = fmaxf(fmaxf(fmaxf(s1[0], s1[1]), fmaxf(s1[2], s1[3])),
                       fmaxf(fmaxf(s1[4], s1[5]), fmaxf(s1[6], s1[7])));
    float lsum = 0.0f;
#pragma unroll
    for (int i = 0; i < 8; i++) { v[i] = expf(v[i] - gmax); lsum += v[i]; }
#pragma unroll
    for (int o = 16; o; o >>= 1) lsum += __shfl_xor_sync(0xffffffffu, lsum, o);
    if (lane == 0) s2[w] = lsum;
    __syncthreads();
    float inv = 1.0f / (s2[0] + s2[1] + s2[2] + s2[3] + s2[4] + s2[5] + s2[6] + s2[7]);
#pragma unroll
    for (int i = 0; i < 8; i++) {
        int c = tid + 256 * i;
        int slot = c >> 9, sx = (c >> 8) & 1, d = c & 255;
        g_ad[sx][m * 1024 + slot * 256 + d] = to_tf32(v[i] * inv * hsm[sx * 256 + d]);
    }
    __syncthreads();
}

// ---------------- merge RED partials + relu ----------------------------------
__device__ __forceinline__ void phase_merge(const RP& P, int bid, int tid) {
#pragma unroll
    for (int j = 0; j < 2; j++) {
        int idx = bid * 256 + tid + j * 65536;     // 131072 outputs
        int s = idx >> 16, r = idx & 65535, n = r & 255;
        float v = __ldcg(&g_rp[0][s][r]) + __ldcg(&g_rp[1][s][r])
                + __ldcg(&g_rp[2][s][r]) + __ldcg(&g_rp[3][s][r])
                + (s ? P.red_t_b : P.red_v_b)[n];
        g_r[s][r] = to_tf32(fmaxf(v, 0.0f));
    }
}

// ---------------- final head (1 row/block) -----------------------------------
__device__ __forceinline__ void phase_final(const RP& P, int bid, int tid, float* scr) {
    float* hrow = scr;
    float* red  = scr + 512;
    int b = bid;
    hrow[tid]       = __ldcg(g_h[0] + b * DD + tid);
    hrow[256 + tid] = __ldcg(g_h[1] + b * DD + tid);
    __syncthreads();
    float acc = P.late0_b[tid];
#pragma unroll 8
    for (int k = 0; k < 512; k++) acc = fmaf(hrow[k], P.late0_w[k * DD + tid], acc);
    float w1a = P.late1_w[tid * 2 + 0], w1b = P.late1_w[tid * 2 + 1];

    red[tid] = acc * w1a;
    __syncthreads();
    for (int st = 128; st; st >>= 1) { if (tid < st) red[tid] += red[tid + st]; __syncthreads(); }
    if (tid == 0) P.out[b * 2 + 0] = red[0] + P.late1_b[0];
    __syncthreads();
    red[tid] = acc * w1b;
    __syncthreads();
    for (int st = 128; st; st >>= 1) { if (tid < st) red[tid] += red[tid + st]; __syncthreads(); }
    if (tid == 0) P.out[b * 2 + 1] = red[0] + P.late1_b[1];
}

// ---------------- prep kernels ------------------------------------------------
__global__ __launch_bounds__(256) void k_perm(RP P) {
    int tid = threadIdx.x, bidx = blockIdx.x;
    // g_wp: 2 x 512 x 1024 (gate-permuted, tf32)
    {
        int base = bidx * 2048 + tid;
#pragma unroll
        for (int j = 0; j < 8; j++) {
            int idx = base + j * 256;              // 1048576
            int s = idx >> 19, r = idx & 524287;
            int k = r >> 10, np = r & 1023;
            const float* src = (k < 256) ? (s ? P.ltW : P.lvW) : (s ? P.ltU : P.lvU);
            g_wp[s][k * 1024 + np] =
                to_tf32(src[(size_t)(k & 255) * 1024 + (np & 3) * 256 + (np >> 2)]);
        }
    }
    // g_attw: 512 x 2048 (tf32)
    {
        int base = bidx * 2048 + tid;
#pragma unroll
        for (int j = 0; j < 8; j++) {
            int idx = base + j * 256;
            g_attw[idx] = to_tf32(P.att_w[idx]);
        }
    }
    // g_redw: 2 x 1024 x 256 (tf32)
    {
        int base = bidx * 1024 + tid;
#pragma unroll
        for (int j = 0; j < 4; j++) {
            int idx = base + j * 256;
            int s = idx >> 18, r = idx & 262143;
            g_redw[s][r] = to_tf32((s ? P.red_t_w : P.red_v_w)[r]);
        }
    }
    // g_bf, g_bpk: 2 x 1024 each
    if (bidx < 2) {
        int s = bidx;
        const float* Vs = s ? P.ltV : P.lvV;
        const float* bp = s ? P.ltb : P.lvb;
#pragma unroll
        for (int q = 0; q < 4; q++) {
            int np = tid * 4 + q;
            int a = (np & 3) * 256 + (np >> 2);
            float acc = 0.0f;
            for (int j = 0; j < 256; j++) acc = fmaf(P.mab_b[j], Vs[j * 1024 + a], acc);
            g_bf[s][np] = acc;
            g_bpk[s][np] = bp[a];
        }
    }
}

__global__ __launch_bounds__(256, 2) void k_prep(RP P) {
    __shared__ float smA[STAGES * 64 * 36];
    __shared__ float smB[STAGES * 32 * 72];
    uint32_t saA = (uint32_t)__cvta_generic_to_shared(smA);
    uint32_t saB = (uint32_t)__cvta_generic_to_shared(smB);
    gemm_pipe<M_PREP, 64, 64>(P, blockIdx.z, 0, blockIdx.y * 64, blockIdx.x * 64, 0,
                              smA, smB, saA, saB);
}

__global__ __launch_bounds__(256, 2) void k_front(RP P) {
    __shared__ float smA[STAGES * 64 * 36];
    __shared__ float smB[STAGES * 32 * 72];
    uint32_t saA = (uint32_t)__cvta_generic_to_shared(smA);
    uint32_t saB = (uint32_t)__cvta_generic_to_shared(smB);
    gemm_pipe<M_FRONT, 64, 64>(P, blockIdx.z, 0, blockIdx.y * 64, blockIdx.x * 64, 0,
                               smA, smB, saA, saB);
}

// ---------------- persistent recurrence kernel (256 blocks, 2/SM) ------------
__global__ __launch_bounds__(256, 2) void k_recur(RP P) {
    __shared__ float smA[STAGES * 64 * 36];
    __shared__ float smB[STAGES * 32 * 72];
    uint32_t saA = (uint32_t)__cvta_generic_to_shared(smA);
    uint32_t saB = (uint32_t)__cvta_generic_to_shared(smB);
    const int bid = blockIdx.x, tid = threadIdx.x;

    for (int i = bid * 256 + tid; i < BB * DD; i += NBLK * 256) {
        g_h[0][i] = 0.f; g_h[1][i] = 0.f;
        g_c[0][i] = 0.f; g_c[1][i] = 0.f;
        g_r[0][i] = 0.f; g_r[1][i] = 0.f;
    }
    gsync();

#pragma unroll 1
    for (int t = 0; t < TT; t++) {
        { // fused LSTHM+ZZV: [x,h|r0,r1]@[Wp|Wf], 2ks x 2s x 4m x 16n (256 blk)
            int ks = bid >> 7, s = (bid >> 6) & 1, r = bid & 63;
            gemm_pipe<M_LSTHM, 64, 64>(P, s, ks, (r >> 4) * 64, (r & 15) * 64, t,
                                       smA, smB, saA, saB);
        }
        gsync();
        phase_gates(P, bid, tid, t);
        gsync();
        if (t < TT - 1) {
            { // ATT split-K: 2ks x 4m x 32n tiles 64x64 (256 blocks)
                int ks = bid >> 7, r = bid & 127;
                gemm_pipe<M_ATT, 64, 64>(P, 0, ks, (r >> 5) * 64, (r & 31) * 64, t,
                                         smA, smB, saA, saB);
            }
            gsync();
            phase_softmax(P, bid, tid, smA);
            gsync();
            { // RED split-K: 2s x 4ks x 8m x 4n tiles 32x64 (256 blocks)
                int s = bid >> 7, ks = (bid >> 5) & 3, r = bid & 31;
                gemm_pipe<M_RED, 32, 64>(P, s, ks, (r >> 2) * 32, (r & 3) * 64, t,
                                         smA, smB, saA, saB);
            }
            gsync();
            phase_merge(P, bid, tid);
            gsync();
        }
    }

    phase_final(P, bid, tid, smA);
}

// ---------------- launch -----------------------------------------------------
extern "C" void kernel_launch(void* const* d_in, const int* in_sizes, int n_in,
                              void* d_out, int out_size) {
    RP P;
    P.xv      = (const float*)d_in[0];
    P.xt      = (const float*)d_in[1];
    P.fc0_w   = (const float*)d_in[2];
    P.fc0_b   = (const float*)d_in[3];
    P.fc1_w   = (const float*)d_in[4];
    P.fc1_b   = (const float*)d_in[5];
    P.lvW     = (const float*)d_in[6];
    P.lvU     = (const float*)d_in[7];
    P.lvV     = (const float*)d_in[8];
    P.lvb     = (const float*)d_in[9];
    P.ltW     = (const float*)d_in[10];
    P.ltU     = (const float*)d_in[11];
    P.ltV     = (const float*)d_in[12];
    P.ltb     = (const float*)d_in[13];
    P.att_w   = (const float*)d_in[14];
    P.att_b   = (const float*)d_in[15];
    P.red_v_w = (const float*)d_in[16];
    P.red_v_b = (const float*)d_in[17];
    P.red_t_w = (const float*)d_in[18];
    P.red_t_b = (const float*)d_in[19];
    P.mab_w   = (const float*)d_in[20];
    P.mab_b   = (const float*)d_in[21];
    P.late0_w = (const float*)d_in[22];
    P.late0_b = (const float*)d_in[23];
    P.late1_w = (const float*)d_in[24];
    P.late1_b = (const float*)d_in[25];
    P.out     = (float*)d_out;

    k_perm<<<512, 256>>>(P);                   // weight permute/convert + biases
    k_prep<<<dim3(16, 8, 2), 256>>>(P);        // Wf = mab_w @ V
    k_front<<<dim3(4, 100, 2), 256>>>(P);      // frontend GEMM
    k_recur<<<NBLK, 256>>>(P);                 // persistent recurrence + head
}

// round 16
// speedup vs baseline: 1.2741x; 1.0474x over previous
#include <cuda_runtime.h>
#include <cstdint>

#define BB 256
#define TT 25
#define PRE 2048
#define DD 256
#define K2D 2048
#define NBLK 256
#define STAGES 3

// ---------------- scratch (device globals) ----------------------------------
__device__ float g_x[2][BB * TT * DD];
__device__ float g_h[2][BB * DD];
__device__ float g_c[2][BB * DD];
__device__ float g_ad[2][BB * 1024];      // attended att*h (tf32)
__device__ float g_r[2][BB * DD];         // relu'd reduction output (tf32)
__device__ float g_sp[2][2][BB * 1024];   // LSTHM partials [ks][s]
__device__ float g_ap[2][BB * K2D];       // ATT partials [ks]
__device__ float g_rp[4][2][BB * DD];     // RED partials [ks][s]
__device__ float g_wp[2][512 * 1024];     // permuted [W;U] (tf32)
__device__ float g_wf[2][512 * 1024];     // mab_w @ V (tf32, packed)
__device__ float g_bf[2][1024];           // mab_b @ V (packed)
__device__ float g_bpk[2][1024];          // lv/lt bias (packed)
__device__ float g_attw[512 * K2D];       // att_w (tf32)
__device__ float g_redw[2][1024 * 256];   // red_{v,t}_w (tf32)

__device__ unsigned g_leafgen[16 * 32];   // per-leaf release lines
__device__ unsigned g_leaf[16 * 32];      // per-leaf arrive counters
__device__ unsigned g_root = 0;

struct RP {
    const float *xv, *xt, *fc0_w, *fc0_b, *fc1_w, *fc1_b;
    const float *lvW, *lvU, *lvV, *lvb, *ltW, *ltU, *ltV, *ltb;
    const float *att_w, *att_b, *red_v_w, *red_v_b, *red_t_w, *red_t_b, *mab_w, *mab_b;
    const float *late0_w, *late0_b, *late1_w, *late1_b;
    float* out;
};

enum { M_FRONT = 0, M_LSTHM, M_ATT, M_RED, M_PREP };

template <int MODE> __host__ __device__ constexpr int kdim() {
    return MODE == M_FRONT ? 2048 : MODE == M_LSTHM ? 512 : 256;
}

// ---------------- grid sync (16 leaves x 16 blocks, broadcast release) -------
__device__ __forceinline__ void gsync() {
    __threadfence();
    __syncthreads();
    if (threadIdx.x == 0) {
        int lf = blockIdx.x >> 4;
        volatile unsigned* lg = &g_leafgen[lf * 32];
        unsigned gen = *lg;
        if (atomicAdd(&g_leaf[lf * 32], 1u) == 15u) {
            g_leaf[lf * 32] = 0;
            __threadfence();
            if (atomicAdd(&g_root, 1u) == 15u) {
                g_root = 0;
                __threadfence();
#pragma unroll
                for (int j = 0; j < 16; j++)
                    ((volatile unsigned*)g_leafgen)[j * 32] = gen + 1;
            } else {
                while (*lg == gen) {}
            }
        } else {
            while (*lg == gen) {}
        }
    }
    __syncthreads();
}

// ---------------- cp.async / tf32 helpers ------------------------------------
__device__ __forceinline__ void cp16(uint32_t dst, const void* src) {
    asm volatile("cp.async.cg.shared.global [%0], [%1], 16;" :: "r"(dst), "l"(src));
}
__device__ __forceinline__ void cp4(uint32_t dst, const void* src) {
    asm volatile("cp.async.ca.shared.global [%0], [%1], 4;" :: "r"(dst), "l"(src));
}
__device__ __forceinline__ void cpcommit() { asm volatile("cp.async.commit_group;"); }
__device__ __forceinline__ void cpwait1()  { asm volatile("cp.async.wait_group 1;"); }

__device__ __forceinline__ float to_tf32(float x) {
    asm("cvt.rna.tf32.f32 %0, %0;" : "+f"(x));
    return x;
}
__device__ __forceinline__ float sigm(float x) { return 1.0f / (1.0f + expf(-x)); }

__device__ __forceinline__ void mma_tf32(float* acc, const float* a, const float* b) {
    asm volatile(
        "mma.sync.aligned.m16n8k8.row.col.f32.tf32.tf32.f32 "
        "{%0,%1,%2,%3}, {%4,%5,%6,%7}, {%8,%9}, {%0,%1,%2,%3};\n"
        : "+f"(acc[0]), "+f"(acc[1]), "+f"(acc[2]), "+f"(acc[3])
        : "r"(__float_as_uint(a[0])), "r"(__float_as_uint(a[1])),
          "r"(__float_as_uint(a[2])), "r"(__float_as_uint(a[3])),
          "r"(__float_as_uint(b[0])), "r"(__float_as_uint(b[1])));
}

// ---------------- A-row pointer (k local to split) ---------------------------
template <int MODE>
__device__ __forceinline__ const float* rowA(const RP& P, int m, int k, int s, int ks, int t) {
    if constexpr (MODE == M_FRONT)      return (s ? P.xt : P.xv) + (size_t)m * PRE + k;
    else if constexpr (MODE == M_LSTHM) {
        // fused [x,h | r0,r1] @ [Wp | Wf], K=1024 split in two 512 halves
        if (ks == 0) return (k < DD) ? g_x[s] + (m * TT + t) * DD + k
                                     : g_h[s] + m * DD + (k - DD);
        else         return (k < DD) ? g_r[0] + m * DD + k
                                     : g_r[1] + m * DD + (k - DD);
    }
    else if constexpr (MODE == M_ATT)   return g_h[ks] + m * DD + k;
    else if constexpr (MODE == M_RED)   return g_ad[s] + m * 1024 + ks * 256 + k;
    else                                return P.mab_w + (size_t)m * 256 + k;  // M_PREP
}

// ---------------- pipelined tf32 MMA GEMM (256 thr, KT=64, 3 stages) ---------
template <int MODE, int BM, int BN>
__device__ __forceinline__ void gemm_pipe(const RP& P, int s, int ks, int m0, int n0, int t,
                                          float* smA, float* smB,
                                          uint32_t saA, uint32_t saB) {
    constexpr int KD = kdim<MODE>();
    constexpr int KT = 64;
    constexpr int NITER = KD / KT;
    constexpr int ABUF = BM * 68;        // A stage: BM x 64k, stride 68
    constexpr int BBUF = KT * 72;        // B stage: 64k x 64n, stride 72
    constexpr int WM = BM / 2, WN = BN / 4;
    constexpr int MT = WM / 16, NT = WN / 8;
    constexpr bool CVT = (MODE == M_FRONT || MODE == M_PREP);

    const int koff = (MODE == M_ATT || MODE == M_RED) ? ks * 256 : 0;
    const int tid = threadIdx.x, lane = tid & 31, wid = tid >> 5;
    const int wm = (wid & 1) * WM, wn = (wid >> 1) * WN;
    const int grp = lane >> 2, thr = lane & 3;

    float acc[MT][NT][4] = {};

    auto issue = [&](int i) {
        if (i < NITER) {
            int buf = i % STAGES;
            int k0 = i * KT;
            uint32_t aA = saA + buf * ABUF * 4;
            uint32_t aB = saB + buf * BBUF * 4;
#pragma unroll
            for (int q = tid; q < BM * 16; q += 256) {          // A: BM x 64k
                int m = q >> 4, kq = (q & 15) * 4;
                cp16(aA + (m * 68 + kq) * 4, rowA<MODE>(P, m0 + m, k0 + kq, s, ks, t));
            }
            if constexpr (MODE == M_PREP) {
#pragma unroll
                for (int q = tid; q < 1024; q += 256) {         // B: V gather (one-time)
                    int k = q >> 4, c4 = (q & 15) * 4;
                    const float* row = (s ? P.ltV : P.lvV) + (size_t)(k0 + k) * 1024;
#pragma unroll
                    for (int j = 0; j < 4; j++) {
                        int n = n0 + c4 + j;
                        cp4(aB + (k * 72 + c4 + j) * 4, row + (n & 3) * 256 + (n >> 2));
                    }
                }
            } else {
#pragma unroll
                for (int q = tid; q < 1024; q += 256) {         // B: 64k x 64n
                    int k = q >> 4, n4 = (q & 15) * 4;
                    int kg = koff + k0 + k;
                    const float* row;
                    if constexpr (MODE == M_FRONT)      row = (s ? P.fc1_w : P.fc0_w) + (size_t)kg * 256;
                    else if constexpr (MODE == M_LSTHM) row = (ks ? g_wf[s] : g_wp[s]) + (size_t)kg * 1024;
                    else if constexpr (MODE == M_ATT)   row = g_attw + (size_t)kg * K2D;
                    else                                row = g_redw[s] + (size_t)kg * 256;
                    cp16(aB + (k * 72 + n4) * 4, row + n0 + n4);
                }
            }
        }
        cpcommit();
    };

    issue(0); issue(1);

    for (int i = 0; i < NITER; i++) {
        cpwait1();
        __syncthreads();
        const float* As = smA + (i % STAGES) * ABUF;
        const float* Bs = smB + (i % STAGES) * BBUF;
#pragma unroll
        for (int kk = 0; kk < KT; kk += 8) {
            float afr[MT][4], bfr[NT][2];
#pragma unroll
            for (int mt = 0; mt < MT; mt++) {
                int mb = wm + mt * 16;
                afr[mt][0] = As[(mb + grp) * 68 + kk + thr];
                afr[mt][1] = As[(mb + grp + 8) * 68 + kk + thr];
                afr[mt][2] = As[(mb + grp) * 68 + kk + thr + 4];
                afr[mt][3] = As[(mb + grp + 8) * 68 + kk + thr + 4];
                if constexpr (CVT) {
                    afr[mt][0] = to_tf32(afr[mt][0]); afr[mt][1] = to_tf32(afr[mt][1]);
                    afr[mt][2] = to_tf32(afr[mt][2]); afr[mt][3] = to_tf32(afr[mt][3]);
                }
            }
#pragma unroll
            for (int nt = 0; nt < NT; nt++) {
                int nb = wn + nt * 8;
                bfr[nt][0] = Bs[(kk + thr) * 72 + nb + grp];
                bfr[nt][1] = Bs[(kk + thr + 4) * 72 + nb + grp];
                if constexpr (CVT) {
                    bfr[nt][0] = to_tf32(bfr[nt][0]); bfr[nt][1] = to_tf32(bfr[nt][1]);
                }
            }
#pragma unroll
            for (int mt = 0; mt < MT; mt++)
#pragma unroll
                for (int nt = 0; nt < NT; nt++)
                    mma_tf32(acc[mt][nt], afr[mt], bfr[nt]);
        }
        issue(i + 2);
    }

    // ---- epilogue ----
#pragma unroll
    for (int mt = 0; mt < MT; mt++)
#pragma unroll
        for (int nt = 0; nt < NT; nt++)
#pragma unroll
            for (int e = 0; e < 4; e++) {
                int m = m0 + wm + mt * 16 + grp + ((e >= 2) ? 8 : 0);
                int n = n0 + wn + nt * 8 + 2 * thr + (e & 1);
                float v = acc[mt][nt][e];
                if constexpr (MODE == M_FRONT)
                    g_x[s][m * DD + n] = to_tf32(v + (s ? P.fc1_b : P.fc0_b)[n]);
                else if constexpr (MODE == M_LSTHM)
                    g_sp[ks][s][m * 1024 + n] = v;
                else if constexpr (MODE == M_ATT)
                    g_ap[ks][m * K2D + n] = v;
                else if constexpr (MODE == M_RED)
                    g_rp[ks][s][m * DD + n] = v;
                else  // M_PREP
                    g_wf[s][m * 1024 + n] = to_tf32(v);
            }
}

// ---------------- gates: merge 2 LSTHM partials, update c,h ------------------
__device__ __forceinline__ void phase_gates(const RP& P, int bid, int tid, int t) {
#pragma unroll
    for (int j = 0; j < 2; j++) {
        int idx = bid * 256 + tid + j * 65536;     // 131072 (s,m,d) triples
        int s = idx >> 16, r = idx & 65535;
        int m = r >> 8, d = r & 255;
        int o4 = m * 1024 + d * 4;
        float4 p0 = __ldcg((const float4*)(g_sp[0][s] + o4));
        float4 p1 = __ldcg((const float4*)(g_sp[1][s] + o4));
        float4 bb = *(const float4*)(g_bpk[s] + d * 4);
        float fx = p0.x + p1.x + bb.x;
        float fy = p0.y + p1.y + bb.y;
        float fz = p0.z + p1.z + bb.z;
        float fw = p0.w + p1.w + bb.w;
        if (t > 0) {
            float4 bf = *(const float4*)(g_bf[s] + d * 4);
            fx += bf.x; fy += bf.y; fz += bf.z; fw += bf.w;
        }
        float f = sigm(fx), ii = sigm(fy), oo = sigm(fz), ch = tanhf(fw);
        float c = f * g_c[s][r] + ii * ch;
        g_c[s][r] = c;
        g_h[s][r] = to_tf32(tanhf(c) * oo);
    }
}

// ---------------- softmax (1 row/block): merge ATT partials + attd -----------
__device__ __forceinline__ void phase_softmax(const RP& P, int bid, int tid, float* hsm) {
    __shared__ float s1[8], s2[8];
    int lane = tid & 31, w = tid >> 5;
    int m = bid;
    hsm[tid]       = __ldcg(g_h[0] + m * DD + tid);
    hsm[256 + tid] = __ldcg(g_h[1] + m * DD + tid);
    __syncthreads();
    float v[8];
    float lmax = -1e30f;
#pragma unroll
    for (int i = 0; i < 8; i++) {
        int c = tid + 256 * i;
        v[i] = __ldcg(g_ap[0] + m * K2D + c) + __ldcg(g_ap[1] + m * K2D + c) + P.att_b[c];
        lmax = fmaxf(lmax, v[i]);
    }
#pragma unroll
    for (int o = 16; o; o >>= 1) lmax = fmaxf(lmax, __shfl_xor_sync(0xffffffffu, lmax, o));
    if (lane == 0) s1[w] = lmax;
    __syncthreads();
    float gmax = fmaxf(fmaxf(fmaxf(s1[0], s1[1]), fmaxf(s1[2], s1[3])),
                       fmaxf(fmaxf(s1[4], s1[5]), fmaxf(s1[6], s1[7])));
    float lsum = 0.0f;
#pragma unroll
    for (int i = 0; i < 8; i++) { v[i] = expf(v[i] - gmax); lsum += v[i]; }
#pragma unroll
    for (int o = 16; o; o >>= 1) lsum += __shfl_xor_sync(0xffffffffu, lsum, o);
    if (lane == 0) s2[w] = lsum;
    __syncthreads();
    float inv = 1.0f / (s2[0] + s2[1] + s2[2] + s2[3] + s2[4] + s2[5] + s2[6] + s2[7]);
#pragma unroll
    for (int i = 0; i < 8; i++) {
        int c = tid + 256 * i;
        int slot = c >> 9, sx = (c >> 8) & 1, d = c & 255;
        g_ad[sx][m * 1024 + slot * 256 + d] = to_tf32(v[i] * inv * hsm[sx * 256 + d]);
    }
    __syncthreads();
}

// ---------------- merge RED partials + relu ----------------------------------
__device__ __forceinline__ void phase_merge(const RP& P, int bid, int tid) {
#pragma unroll
    for (int j = 0; j < 2; j++) {
        int idx = bid * 256 + tid + j * 65536;     // 131072 outputs
        int s = idx >> 16, r = idx & 65535, n = r & 255;
        float v = __ldcg(&g_rp[0][s][r]) + __ldcg(&g_rp[1][s][r])
                + __ldcg(&g_rp[2][s][r]) + __ldcg(&g_rp[3][s][r])
                + (s ? P.red_t_b : P.red_v_b)[n];
        g_r[s][r] = to_tf32(fmaxf(v, 0.0f));
    }
}

// ---------------- final head (1 row/block) -----------------------------------
__device__ __forceinline__ void phase_final(const RP& P, int bid, int tid, float* scr) {
    float* hrow = scr;
    float* red  = scr + 512;
    int b = bid;
    hrow[tid]       = __ldcg(g_h[0] + b * DD + tid);
    hrow[256 + tid] = __ldcg(g_h[1] + b * DD + tid);
    __syncthreads();
    float acc = P.late0_b[tid];
#pragma unroll 8
    for (int k = 0; k < 512; k++) acc = fmaf(hrow[k], P.late0_w[k * DD + tid], acc);
    float w1a = P.late1_w[tid * 2 + 0], w1b = P.late1_w[tid * 2 + 1];

    red[tid] = acc * w1a;
    __syncthreads();
    for (int st = 128; st; st >>= 1) { if (tid < st) red[tid] += red[tid + st]; __syncthreads(); }
    if (tid == 0) P.out[b * 2 + 0] = red[0] + P.late1_b[0];
    __syncthreads();
    red[tid] = acc * w1b;
    __syncthreads();
    for (int st = 128; st; st >>= 1) { if (tid < st) red[tid] += red[tid + st]; __syncthreads(); }
    if (tid == 0) P.out[b * 2 + 1] = red[0] + P.late1_b[1];
}

// ---------------- prep kernels ------------------------------------------------
__global__ __launch_bounds__(256) void k_perm(RP P) {
    int tid = threadIdx.x, bidx = blockIdx.x;
    // g_wp: 2 x 512 x 1024 (gate-permuted, tf32)
    {
        int base = bidx * 2048 + tid;
#pragma unroll
        for (int j = 0; j < 8; j++) {
            int idx = base + j * 256;              // 1048576
            int s = idx >> 19, r = idx & 524287;
            int k = r >> 10, np = r & 1023;
            const float* src = (k < 256) ? (s ? P.ltW : P.lvW) : (s ? P.ltU : P.lvU);
            g_wp[s][k * 1024 + np] =
                to_tf32(src[(size_t)(k & 255) * 1024 + (np & 3) * 256 + (np >> 2)]);
        }
    }
    // g_attw: 512 x 2048 (tf32)
    {
        int base = bidx * 2048 + tid;
#pragma unroll
        for (int j = 0; j < 8; j++) {
            int idx = base + j * 256;
            g_attw[idx] = to_tf32(P.att_w[idx]);
        }
    }
    // g_redw: 2 x 1024 x 256 (tf32)
    {
        int base = bidx * 1024 + tid;
#pragma unroll
        for (int j = 0; j < 4; j++) {
            int idx = base + j * 256;
            int s = idx >> 18, r = idx & 262143;
            g_redw[s][r] = to_tf32((s ? P.red_t_w : P.red_v_w)[r]);
        }
    }
    // g_bf, g_bpk: 2 x 1024 each
    if (bidx < 2) {
        int s = bidx;
        const float* Vs = s ? P.ltV : P.lvV;
        const float* bp = s ? P.ltb : P.lvb;
#pragma unroll
        for (int q = 0; q < 4; q++) {
            int np = tid * 4 + q;
            int a = (np & 3) * 256 + (np >> 2);
            float acc = 0.0f;
            for (int j = 0; j < 256; j++) acc = fmaf(P.mab_b[j], Vs[j * 1024 + a], acc);
            g_bf[s][np] = acc;
            g_bpk[s][np] = bp[a];
        }
    }
}

__global__ __launch_bounds__(256, 2) void k_prep(RP P) {
    __shared__ float smA[STAGES * 64 * 68];
    __shared__ float smB[STAGES * 64 * 72];
    uint32_t saA = (uint32_t)__cvta_generic_to_shared(smA);
    uint32_t saB = (uint32_t)__cvta_generic_to_shared(smB);
    gemm_pipe<M_PREP, 64, 64>(P, blockIdx.z, 0, blockIdx.y * 64, blockIdx.x * 64, 0,
                              smA, smB, saA, saB);
}

__global__ __launch_bounds__(256, 2) void k_front(RP P) {
    __shared__ float smA[STAGES * 64 * 68];
    __shared__ float smB[STAGES * 64 * 72];
    uint32_t saA = (uint32_t)__cvta_generic_to_shared(smA);
    uint32_t saB = (uint32_t)__cvta_generic_to_shared(smB);
    gemm_pipe<M_FRONT, 64, 64>(P, blockIdx.z, 0, blockIdx.y * 64, blockIdx.x * 64, 0,
                               smA, smB, saA, saB);
}

// ---------------- persistent recurrence kernel (256 blocks, 2/SM) ------------
__global__ __launch_bounds__(256, 2) void k_recur(RP P) {
    __shared__ float smA[STAGES * 64 * 68];
    __shared__ float smB[STAGES * 64 * 72];
    uint32_t saA = (uint32_t)__cvta_generic_to_shared(smA);
    uint32_t saB = (uint32_t)__cvta_generic_to_shared(smB);
    const int bid = blockIdx.x, tid = threadIdx.x;

    for (int i = bid * 256 + tid; i < BB * DD; i += NBLK * 256) {
        g_h[0][i] = 0.f; g_h[1][i] = 0.f;
        g_c[0][i] = 0.f; g_c[1][i] = 0.f;
        g_r[0][i] = 0.f; g_r[1][i] = 0.f;
    }
    gsync();

#pragma unroll 1
    for (int t = 0; t < TT; t++) {
        { // fused LSTHM+ZZV: [x,h|r0,r1]@[Wp|Wf], 2ks x 2s x 4m x 16n (256 blk)
            int ks = bid >> 7, s = (bid >> 6) & 1, r = bid & 63;
            gemm_pipe<M_LSTHM, 64, 64>(P, s, ks, (r >> 4) * 64, (r & 15) * 64, t,
                                       smA, smB, saA, saB);
        }
        gsync();
        phase_gates(P, bid, tid, t);
        gsync();
        if (t < TT - 1) {
            { // ATT split-K: 2ks x 4m x 32n tiles 64x64 (256 blocks)
                int ks = bid >> 7, r = bid & 127;
                gemm_pipe<M_ATT, 64, 64>(P, 0, ks, (r >> 5) * 64, (r & 31) * 64, t,
                                         smA, smB, saA, saB);
            }
            gsync();
            phase_softmax(P, bid, tid, smA);
            gsync();
            { // RED split-K: 2s x 4ks x 8m x 4n tiles 32x64 (256 blocks)
                int s = bid >> 7, ks = (bid >> 5) & 3, r = bid & 31;
                gemm_pipe<M_RED, 32, 64>(P, s, ks, (r >> 2) * 32, (r & 3) * 64, t,
                                         smA, smB, saA, saB);
            }
            gsync();
            phase_merge(P, bid, tid);
            gsync();
        }
    }

    phase_final(P, bid, tid, smA);
}

// ---------------- launch -----------------------------------------------------
extern "C" void kernel_launch(void* const* d_in, const int* in_sizes, int n_in,
                              void* d_out, int out_size) {
    RP P;
    P.xv      = (const float*)d_in[0];
    P.xt      = (const float*)d_in[1];
    P.fc0_w   = (const float*)d_in[2];
    P.fc0_b   = (const float*)d_in[3];
    P.fc1_w   = (const float*)d_in[4];
    P.fc1_b   = (const float*)d_in[5];
    P.lvW     = (const float*)d_in[6];
    P.lvU     = (const float*)d_in[7];
    P.lvV     = (const float*)d_in[8];
    P.lvb     = (const float*)d_in[9];
    P.ltW     = (const float*)d_in[10];
    P.ltU     = (const float*)d_in[11];
    P.ltV     = (const float*)d_in[12];
    P.ltb     = (const float*)d_in[13];
    P.att_w   = (const float*)d_in[14];
    P.att_b   = (const float*)d_in[15];
    P.red_v_w = (const float*)d_in[16];
    P.red_v_b = (const float*)d_in[17];
    P.red_t_w = (const float*)d_in[18];
    P.red_t_b = (const float*)d_in[19];
    P.mab_w   = (const float*)d_in[20];
    P.mab_b   = (const float*)d_in[21];
    P.late0_w = (const float*)d_in[22];
    P.late0_b = (const float*)d_in[23];
    P.late1_w = (const float*)d_in[24];
    P.late1_b = (const float*)d_in[25];
    P.out     = (float*)d_out;

    k_perm<<<512, 256>>>(P);                   // weight permute/convert + biases
    k_prep<<<dim3(16, 8, 2), 256>>>(P);        // Wf = mab_w @ V
    k_front<<<dim3(4, 100, 2), 256>>>(P);      // frontend GEMM
    k_recur<<<NBLK, 256>>>(P);                 // persistent recurrence + head
}

// round 17
// speedup vs baseline: 1.4025x; 1.1008x over previous
#include <cuda_runtime.h>
#include <cstdint>

#define BB 256
#define TT 25
#define PRE 2048
#define DD 256
#define K2D 2048
#define NBLK 256
#define STAGES 3

// ---------------- scratch (device globals) ----------------------------------
__device__ float g_x[2][BB * TT * DD];
__device__ float g_h[2][BB * DD];
__device__ float g_c[2][BB * DD];
__device__ float g_ad[2][BB * 1024];      // attended att*h (tf32)
__device__ float g_r[2][BB * DD];         // relu'd reduction output (tf32)
__device__ float g_sp[2][2][BB * 1024];   // LSTHM partials [ks][s]
__device__ float g_ap[2][BB * K2D];       // ATT partials [ks]
__device__ float g_rp[4][2][BB * DD];     // RED partials [ks][s]
__device__ float g_wp[2][512 * 1024];     // permuted [W;U] (tf32)
__device__ float g_wf[2][512 * 1024];     // mab_w @ V (tf32, packed)
__device__ float g_bf[2][1024];           // mab_b @ V (packed)
__device__ float g_bpk[2][1024];          // lv/lt bias (packed)
__device__ float g_attw[512 * K2D];       // att_w (tf32)
__device__ float g_redw[2][1024 * 256];   // red_{v,t}_w (tf32)

__device__ unsigned g_leafgen[16 * 32];   // per-leaf release lines
__device__ unsigned g_leaf[16 * 32];      // per-leaf arrive counters
__device__ unsigned g_root = 0;

struct RP {
    const float *xv, *xt, *fc0_w, *fc0_b, *fc1_w, *fc1_b;
    const float *lvW, *lvU, *lvV, *lvb, *ltW, *ltU, *ltV, *ltb;
    const float *att_w, *att_b, *red_v_w, *red_v_b, *red_t_w, *red_t_b, *mab_w, *mab_b;
    const float *late0_w, *late0_b, *late1_w, *late1_b;
    float* out;
};

enum { M_FRONT = 0, M_LSTHM, M_ATT, M_RED, M_PREP };

template <int MODE> __host__ __device__ constexpr int kdim() {
    return MODE == M_FRONT ? 2048 : MODE == M_LSTHM ? 512 : 256;
}

// ---------------- grid sync (16 leaves x 16 blocks, broadcast release) -------
__device__ __forceinline__ void gsync() {
    __threadfence();
    __syncthreads();
    if (threadIdx.x == 0) {
        int lf = blockIdx.x >> 4;
        volatile unsigned* lg = &g_leafgen[lf * 32];
        unsigned gen = *lg;
        if (atomicAdd(&g_leaf[lf * 32], 1u) == 15u) {
            g_leaf[lf * 32] = 0;
            __threadfence();
            if (atomicAdd(&g_root, 1u) == 15u) {
                g_root = 0;
                __threadfence();
#pragma unroll
                for (int j = 0; j < 16; j++)
                    ((volatile unsigned*)g_leafgen)[j * 32] = gen + 1;
            } else {
                while (*lg == gen) {}
            }
        } else {
            while (*lg == gen) {}
        }
    }
    __syncthreads();
}

// ---------------- cp.async / tf32 helpers ------------------------------------
__device__ __forceinline__ void cp16(uint32_t dst, const void* src) {
    asm volatile("cp.async.cg.shared.global [%0], [%1], 16;" :: "r"(dst), "l"(src));
}
__device__ __forceinline__ void cp4(uint32_t dst, const void* src) {
    asm volatile("cp.async.ca.shared.global [%0], [%1], 4;" :: "r"(dst), "l"(src));
}
__device__ __forceinline__ void cpcommit() { asm volatile("cp.async.commit_group;"); }
__device__ __forceinline__ void cpwait1()  { asm volatile("cp.async.wait_group 1;"); }

__device__ __forceinline__ float to_tf32(float x) {
    asm("cvt.rna.tf32.f32 %0, %0;" : "+f"(x));
    return x;
}
__device__ __forceinline__ float sigm(float x) { return 1.0f / (1.0f + expf(-x)); }

__device__ __forceinline__ void mma_tf32(float* acc, const float* a, const float* b) {
    asm volatile(
        "mma.sync.aligned.m16n8k8.row.col.f32.tf32.tf32.f32 "
        "{%0,%1,%2,%3}, {%4,%5,%6,%7}, {%8,%9}, {%0,%1,%2,%3};\n"
        : "+f"(acc[0]), "+f"(acc[1]), "+f"(acc[2]), "+f"(acc[3])
        : "r"(__float_as_uint(a[0])), "r"(__float_as_uint(a[1])),
          "r"(__float_as_uint(a[2])), "r"(__float_as_uint(a[3])),
          "r"(__float_as_uint(b[0])), "r"(__float_as_uint(b[1])));
}

// ---------------- A-row pointer (k local to split) ---------------------------
template <int MODE>
__device__ __forceinline__ const float* rowA(const RP& P, int m, int k, int s, int ks, int t) {
    if constexpr (MODE == M_FRONT)      return (s ? P.xt : P.xv) + (size_t)m * PRE + k;
    else if constexpr (MODE == M_LSTHM) {
        // fused [x,h | r0,r1] @ [Wp | Wf], K=1024 split in two 512 halves
        if (ks == 0) return (k < DD) ? g_x[s] + (m * TT + t) * DD + k
                                     : g_h[s] + m * DD + (k - DD);
        else         return (k < DD) ? g_r[0] + m * DD + k
                                     : g_r[1] + m * DD + (k - DD);
    }
    else if constexpr (MODE == M_ATT)   return g_h[ks] + m * DD + k;
    else if constexpr (MODE == M_RED)   return g_ad[s] + m * 1024 + ks * 256 + k;
    else                                return P.mab_w + (size_t)m * 256 + k;  // M_PREP
}

// ---------------- pipelined tf32 MMA GEMM (256 thr, KT=64, 3 stages) ---------
template <int MODE, int BM, int BN>
__device__ __forceinline__ void gemm_pipe(const RP& P, int s, int ks, int m0, int n0, int t,
                                          float* smA, float* smB,
                                          uint32_t saA, uint32_t saB) {
    constexpr int KD = kdim<MODE>();
    constexpr int KT = 64;
    constexpr int NITER = KD / KT;
    constexpr int ABUF = BM * 68;        // A stage: BM x 64k, stride 68
    constexpr int BBUF = KT * 72;        // B stage: 64k x 64n, stride 72
    constexpr int WM = BM / 2, WN = BN / 4;
    constexpr int MT = WM / 16, NT = WN / 8;
    constexpr bool CVT = (MODE == M_FRONT || MODE == M_PREP);

    const int koff = (MODE == M_ATT || MODE == M_RED) ? ks * 256 : 0;
    const int tid = threadIdx.x, lane = tid & 31, wid = tid >> 5;
    const int wm = (wid & 1) * WM, wn = (wid >> 1) * WN;
    const int grp = lane >> 2, thr = lane & 3;

    float acc[MT][NT][4] = {};

    auto issue = [&](int i) {
        if (i < NITER) {
            int buf = i % STAGES;
            int k0 = i * KT;
            uint32_t aA = saA + buf * ABUF * 4;
            uint32_t aB = saB + buf * BBUF * 4;
#pragma unroll
            for (int q = tid; q < BM * 16; q += 256) {          // A: BM x 64k
                int m = q >> 4, kq = (q & 15) * 4;
                cp16(aA + (m * 68 + kq) * 4, rowA<MODE>(P, m0 + m, k0 + kq, s, ks, t));
            }
            if constexpr (MODE == M_PREP) {
#pragma unroll
                for (int q = tid; q < 1024; q += 256) {         // B: V gather (one-time)
                    int k = q >> 4, c4 = (q & 15) * 4;
                    const float* row = (s ? P.ltV : P.lvV) + (size_t)(k0 + k) * 1024;
#pragma unroll
                    for (int j = 0; j < 4; j++) {
                        int n = n0 + c4 + j;
                        cp4(aB + (k * 72 + c4 + j) * 4, row + (n & 3) * 256 + (n >> 2));
                    }
                }
            } else {
#pragma unroll
                for (int q = tid; q < 1024; q += 256) {         // B: 64k x 64n
                    int k = q >> 4, n4 = (q & 15) * 4;
                    int kg = koff + k0 + k;
                    const float* row;
                    if constexpr (MODE == M_FRONT)      row = (s ? P.fc1_w : P.fc0_w) + (size_t)kg * 256;
                    else if constexpr (MODE == M_LSTHM) row = (ks ? g_wf[s] : g_wp[s]) + (size_t)kg * 1024;
                    else if constexpr (MODE == M_ATT)   row = g_attw + (size_t)kg * K2D;
                    else                                row = g_redw[s] + (size_t)kg * 256;
                    cp16(aB + (k * 72 + n4) * 4, row + n0 + n4);
                }
            }
        }
        cpcommit();
    };

    issue(0); issue(1);

    for (int i = 0; i < NITER; i++) {
        cpwait1();
        __syncthreads();
        const float* As = smA + (i % STAGES) * ABUF;
        const float* Bs = smB + (i % STAGES) * BBUF;
#pragma unroll
        for (int kk = 0; kk < KT; kk += 8) {
            float afr[MT][4], bfr[NT][2];
#pragma unroll
            for (int mt = 0; mt < MT; mt++) {
                int mb = wm + mt * 16;
                afr[mt][0] = As[(mb + grp) * 68 + kk + thr];
                afr[mt][1] = As[(mb + grp + 8) * 68 + kk + thr];
                afr[mt][2] = As[(mb + grp) * 68 + kk + thr + 4];
                afr[mt][3] = As[(mb + grp + 8) * 68 + kk + thr + 4];
                if constexpr (CVT) {
                    afr[mt][0] = to_tf32(afr[mt][0]); afr[mt][1] = to_tf32(afr[mt][1]);
                    afr[mt][2] = to_tf32(afr[mt][2]); afr[mt][3] = to_tf32(afr[mt][3]);
                }
            }
#pragma unroll
            for (int nt = 0; nt < NT; nt++) {
                int nb = wn + nt * 8;
                bfr[nt][0] = Bs[(kk + thr) * 72 + nb + grp];
                bfr[nt][1] = Bs[(kk + thr + 4) * 72 + nb + grp];
                if constexpr (CVT) {
                    bfr[nt][0] = to_tf32(bfr[nt][0]); bfr[nt][1] = to_tf32(bfr[nt][1]);
                }
            }
#pragma unroll
            for (int mt = 0; mt < MT; mt++)
#pragma unroll
                for (int nt = 0; nt < NT; nt++)
                    mma_tf32(acc[mt][nt], afr[mt], bfr[nt]);
        }
        issue(i + 2);
    }

    // ---- epilogue ----
#pragma unroll
    for (int mt = 0; mt < MT; mt++)
#pragma unroll
        for (int nt = 0; nt < NT; nt++)
#pragma unroll
            for (int e = 0; e < 4; e++) {
                int m = m0 + wm + mt * 16 + grp + ((e >= 2) ? 8 : 0);
                int n = n0 + wn + nt * 8 + 2 * thr + (e & 1);
                float v = acc[mt][nt][e];
                if constexpr (MODE == M_FRONT)
                    g_x[s][m * DD + n] = to_tf32(v + (s ? P.fc1_b : P.fc0_b)[n]);
                else if constexpr (MODE == M_LSTHM)
                    g_sp[ks][s][m * 1024 + n] = v;
                else if constexpr (MODE == M_ATT)
                    g_ap[ks][m * K2D + n] = v;
                else if constexpr (MODE == M_RED)
                    g_rp[ks][s][m * DD + n] = v;
                else  // M_PREP
                    g_wf[s][m * 1024 + n] = to_tf32(v);
            }
}

// ---------------- gates: merge 2 LSTHM partials, update c,h ------------------
__device__ __forceinline__ void phase_gates(const RP& P, int bid, int tid, int t) {
#pragma unroll
    for (int j = 0; j < 2; j++) {
        int idx = bid * 256 + tid + j * 65536;     // 131072 (s,m,d) triples
        int s = idx >> 16, r = idx & 65535;
        int m = r >> 8, d = r & 255;
        int o4 = m * 1024 + d * 4;
        float4 p0 = __ldcg((const float4*)(g_sp[0][s] + o4));
        float4 p1 = __ldcg((const float4*)(g_sp[1][s] + o4));
        float4 bb = *(const float4*)(g_bpk[s] + d * 4);
        float fx = p0.x + p1.x + bb.x;
        float fy = p0.y + p1.y + bb.y;
        float fz = p0.z + p1.z + bb.z;
        float fw = p0.w + p1.w + bb.w;
        if (t > 0) {
            float4 bf = *(const float4*)(g_bf[s] + d * 4);
            fx += bf.x; fy += bf.y; fz += bf.z; fw += bf.w;
        }
        float f = sigm(fx), ii = sigm(fy), oo = sigm(fz), ch = tanhf(fw);
        float c = f * g_c[s][r] + ii * ch;
        g_c[s][r] = c;
        g_h[s][r] = to_tf32(tanhf(c) * oo);
    }
}

// ---------------- softmax (1 row/block): merge ATT partials + attd -----------
// No max-subtraction: |logit| <= sum|att_w col| <= ~8 (|h|<=1), exp is safe.
// softmax(x) == exp(x)/sum(exp(x)) exactly; fp delta is ulp-level.
__device__ __forceinline__ void phase_softmax(const RP& P, int bid, int tid, float* hsm) {
    __shared__ float s2[8];
    int lane = tid & 31, w = tid >> 5;
    int m = bid;
    hsm[tid]       = __ldcg(g_h[0] + m * DD + tid);
    hsm[256 + tid] = __ldcg(g_h[1] + m * DD + tid);
    __syncthreads();
    float v[8];
    float lsum = 0.0f;
#pragma unroll
    for (int i = 0; i < 8; i++) {
        int c = tid + 256 * i;
        float lg = __ldcg(g_ap[0] + m * K2D + c) + __ldcg(g_ap[1] + m * K2D + c) + P.att_b[c];
        v[i] = expf(lg);
        lsum += v[i];
    }
#pragma unroll
    for (int o = 16; o; o >>= 1) lsum += __shfl_xor_sync(0xffffffffu, lsum, o);
    if (lane == 0) s2[w] = lsum;
    __syncthreads();
    float inv = 1.0f / (s2[0] + s2[1] + s2[2] + s2[3] + s2[4] + s2[5] + s2[6] + s2[7]);
#pragma unroll
    for (int i = 0; i < 8; i++) {
        int c = tid + 256 * i;
        int slot = c >> 9, sx = (c >> 8) & 1, d = c & 255;
        g_ad[sx][m * 1024 + slot * 256 + d] = to_tf32(v[i] * inv * hsm[sx * 256 + d]);
    }
    __syncthreads();
}

// ---------------- merge RED partials + relu ----------------------------------
__device__ __forceinline__ void phase_merge(const RP& P, int bid, int tid) {
#pragma unroll
    for (int j = 0; j < 2; j++) {
        int idx = bid * 256 + tid + j * 65536;     // 131072 outputs
        int s = idx >> 16, r = idx & 65535, n = r & 255;
        float v = __ldcg(&g_rp[0][s][r]) + __ldcg(&g_rp[1][s][r])
                + __ldcg(&g_rp[2][s][r]) + __ldcg(&g_rp[3][s][r])
                + (s ? P.red_t_b : P.red_v_b)[n];
        g_r[s][r] = to_tf32(fmaxf(v, 0.0f));
    }
}

// ---------------- final head (1 row/block) -----------------------------------
__device__ __forceinline__ void phase_final(const RP& P, int bid, int tid, float* scr) {
    float* hrow = scr;
    float* red  = scr + 512;
    int b = bid;
    hrow[tid]       = __ldcg(g_h[0] + b * DD + tid);
    hrow[256 + tid] = __ldcg(g_h[1] + b * DD + tid);
    __syncthreads();
    float acc = P.late0_b[tid];
#pragma unroll 8
    for (int k = 0; k < 512; k++) acc = fmaf(hrow[k], P.late0_w[k * DD + tid], acc);
    float w1a = P.late1_w[tid * 2 + 0], w1b = P.late1_w[tid * 2 + 1];

    red[tid] = acc * w1a;
    __syncthreads();
    for (int st = 128; st; st >>= 1) { if (tid < st) red[tid] += red[tid + st]; __syncthreads(); }
    if (tid == 0) P.out[b * 2 + 0] = red[0] + P.late1_b[0];
    __syncthreads();
    red[tid] = acc * w1b;
    __syncthreads();
    for (int st = 128; st; st >>= 1) { if (tid < st) red[tid] += red[tid + st]; __syncthreads(); }
    if (tid == 0) P.out[b * 2 + 1] = red[0] + P.late1_b[1];
}

// ---------------- perm job (weight permute/convert + biases) -----------------
__device__ __forceinline__ void perm_job(const RP& P, int bidx, int tid) {
    // g_wp: 2 x 512 x 1024 (gate-permuted, tf32)
    {
        int base = bidx * 2048 + tid;
#pragma unroll
        for (int j = 0; j < 8; j++) {
            int idx = base + j * 256;              // 1048576
            int s = idx >> 19, r = idx & 524287;
            int k = r >> 10, np = r & 1023;
            const float* src = (k < 256) ? (s ? P.ltW : P.lvW) : (s ? P.ltU : P.lvU);
            g_wp[s][k * 1024 + np] =
                to_tf32(src[(size_t)(k & 255) * 1024 + (np & 3) * 256 + (np >> 2)]);
        }
    }
    // g_attw: 512 x 2048 (tf32)
    {
        int base = bidx * 2048 + tid;
#pragma unroll
        for (int j = 0; j < 8; j++) {
            int idx = base + j * 256;
            g_attw[idx] = to_tf32(P.att_w[idx]);
        }
    }
    // g_redw: 2 x 1024 x 256 (tf32)
    {
        int base = bidx * 1024 + tid;
#pragma unroll
        for (int j = 0; j < 4; j++) {
            int idx = base + j * 256;
            int s = idx >> 18, r = idx & 262143;
            g_redw[s][r] = to_tf32((s ? P.red_t_w : P.red_v_w)[r]);
        }
    }
    // g_bf, g_bpk: 2 x 1024 each
    if (bidx < 2) {
        int s = bidx;
        const float* Vs = s ? P.ltV : P.lvV;
        const float* bp = s ? P.ltb : P.lvb;
#pragma unroll
        for (int q = 0; q < 4; q++) {
            int np = tid * 4 + q;
            int a = (np & 3) * 256 + (np >> 2);
            float acc = 0.0f;
            for (int j = 0; j < 256; j++) acc = fmaf(P.mab_b[j], Vs[j * 1024 + a], acc);
            g_bf[s][np] = acc;
            g_bpk[s][np] = bp[a];
        }
    }
}

// ---------------- fused pre-kernel: front | prep | perm (independent jobs) ---
__global__ __launch_bounds__(256, 2) void k_pre(RP P) {
    __shared__ float smA[STAGES * 64 * 68];
    __shared__ float smB[STAGES * 64 * 72];
    uint32_t saA = (uint32_t)__cvta_generic_to_shared(smA);
    uint32_t saB = (uint32_t)__cvta_generic_to_shared(smB);
    int b = blockIdx.x;
    if (b < 800) {
        // front: 4n x 100m x 2s tiles of 64x64
        int nx = b & 3, my = (b >> 2) % 100, s = b / 400;
        gemm_pipe<M_FRONT, 64, 64>(P, s, 0, my * 64, nx * 64, 0, smA, smB, saA, saB);
    } else if (b < 1056) {
        // prep: 16n x 8m x 2s tiles of 64x64 (Wf = mab_w @ V)
        int q = b - 800;
        int nx = q & 15, my = (q >> 4) & 7, s = q >> 7;
        gemm_pipe<M_PREP, 64, 64>(P, s, 0, my * 64, nx * 64, 0, smA, smB, saA, saB);
    } else {
        perm_job(P, b - 1056, threadIdx.x);
    }
}

// ---------------- persistent recurrence kernel (256 blocks, 2/SM) ------------
__global__ __launch_bounds__(256, 2) void k_recur(RP P) {
    __shared__ float smA[STAGES * 64 * 68];
    __shared__ float smB[STAGES * 64 * 72];
    uint32_t saA = (uint32_t)__cvta_generic_to_shared(smA);
    uint32_t saB = (uint32_t)__cvta_generic_to_shared(smB);
    const int bid = blockIdx.x, tid = threadIdx.x;

    for (int i = bid * 256 + tid; i < BB * DD; i += NBLK * 256) {
        g_h[0][i] = 0.f; g_h[1][i] = 0.f;
        g_c[0][i] = 0.f; g_c[1][i] = 0.f;
        g_r[0][i] = 0.f; g_r[1][i] = 0.f;
    }
    gsync();

#pragma unroll 1
    for (int t = 0; t < TT; t++) {
        { // fused LSTHM+ZZV: [x,h|r0,r1]@[Wp|Wf], 2ks x 2s x 4m x 16n (256 blk)
            int ks = bid >> 7, s = (bid >> 6) & 1, r = bid & 63;
            gemm_pipe<M_LSTHM, 64, 64>(P, s, ks, (r >> 4) * 64, (r & 15) * 64, t,
                                       smA, smB, saA, saB);
        }
        gsync();
        phase_gates(P, bid, tid, t);
        gsync();
        if (t < TT - 1) {
            { // ATT split-K: 2ks x 4m x 32n tiles 64x64 (256 blocks)
                int ks = bid >> 7, r = bid & 127;
                gemm_pipe<M_ATT, 64, 64>(P, 0, ks, (r >> 5) * 64, (r & 31) * 64, t,
                                         smA, smB, saA, saB);
            }
            gsync();
            phase_softmax(P, bid, tid, smA);
            gsync();
            { // RED split-K: 2s x 4ks x 8m x 4n tiles 32x64 (256 blocks)
                int s = bid >> 7, ks = (bid >> 5) & 3, r = bid & 31;
                gemm_pipe<M_RED, 32, 64>(P, s, ks, (r >> 2) * 32, (r & 3) * 64, t,
                                         smA, smB, saA, saB);
            }
            gsync();
            phase_merge(P, bid, tid);
            gsync();
        }
    }

    phase_final(P, bid, tid, smA);
}

// ---------------- launch -----------------------------------------------------
extern "C" void kernel_launch(void* const* d_in, const int* in_sizes, int n_in,
                              void* d_out, int out_size) {
    RP P;
    P.xv      = (const float*)d_in[0];
    P.xt      = (const float*)d_in[1];
    P.fc0_w   = (const float*)d_in[2];
    P.fc0_b   = (const float*)d_in[3];
    P.fc1_w   = (const float*)d_in[4];
    P.fc1_b   = (const float*)d_in[5];
    P.lvW     = (const float*)d_in[6];
    P.lvU     = (const float*)d_in[7];
    P.lvV     = (const float*)d_in[8];
    P.lvb     = (const float*)d_in[9];
    P.ltW     = (const float*)d_in[10];
    P.ltU     = (const float*)d_in[11];
    P.ltV     = (const float*)d_in[12];
    P.ltb     = (const float*)d_in[13];
    P.att_w   = (const float*)d_in[14];
    P.att_b   = (const float*)d_in[15];
    P.red_v_w = (const float*)d_in[16];
    P.red_v_b = (const float*)d_in[17];
    P.red_t_w = (const float*)d_in[18];
    P.red_t_b = (const float*)d_in[19];
    P.mab_w   = (const float*)d_in[20];
    P.mab_b   = (const float*)d_in[21];
    P.late0_w = (const float*)d_in[22];
    P.late0_b = (const float*)d_in[23];
    P.late1_w = (const float*)d_in[24];
    P.late1_b = (const float*)d_in[25];
    P.out     = (float*)d_out;

    k_pre<<<1568, 256>>>(P);       // front | prep | perm, concurrent
    k_recur<<<NBLK, 256>>>(P);     // persistent recurrence + head
}